// round 1
// baseline (speedup 1.0000x reference)
#include <cuda_runtime.h>
#include <math.h>

// Problem constants
constexpr int B_ = 2, S_ = 1024, D_ = 1024, N_ = 16, H_ = 64;
constexpr float NORM_ = 0.125f;       // 1/sqrt(64)
constexpr float BIGC_ = 1000000.0f;
constexpr float LNEPS_ = 1e-5f;

// Scratch (static device globals — no runtime allocation)
__device__ float g_qh[B_ * S_ * D_];          // [B,S,N,H]  8 MB
__device__ float g_kh[B_ * S_ * D_];          // [B,S,N,H] -> becomes KS = kh + r
__device__ float g_vh[B_ * S_ * D_];          // [B,S,N,H]
__device__ float g_r [S_ * D_];               // [S,N,H]    4 MB
__device__ float g_cvec[B_ * N_ * S_];        // per-key additive bias
__device__ float g_scores[B_ * N_ * S_ * S_]; // [B*N,S,S]  134 MB
__device__ float g_out[B_ * S_ * D_];         // attention out [B,S,N,H]

// ---------------------------------------------------------------------------
// Generic batched row-major SGEMM: C = A * B (+ colBias) (+ resid)
// Batch z decodes as (bo = z / nInner, bi = z % nInner); each operand offset
// = bo*sOuter + bi*sInner. Requires M%BM==0, N%BN==0, K%BK==0.
// ---------------------------------------------------------------------------
template <int BM, int BN, int BK, int TM, int TN>
__global__ void __launch_bounds__((BM / TM) * (BN / TN))
sgemm_nn_kernel(const float* __restrict__ A, const float* __restrict__ Bm,
                float* __restrict__ C, int M, int N, int K,
                int lda, int ldb, int ldc,
                int nInner,
                long long aOut, long long aIn,
                long long bOut, long long bIn,
                long long cOut, long long cIn,
                const float* __restrict__ colBias,
                const float* __restrict__ resid, int ldr)
{
    constexpr int NT = (BM / TM) * (BN / TN);
    constexpr int TX = BN / TN;
    __shared__ float As[BK][BM];
    __shared__ float Bs[BK][BN];

    const int z = blockIdx.z;
    const int bo = z / nInner, bi = z % nInner;
    A  += bo * aOut + bi * aIn;
    Bm += bo * bOut + bi * bIn;
    C  += bo * cOut + bi * cIn;

    const int m0 = blockIdx.y * BM, n0 = blockIdx.x * BN;
    const int tid = threadIdx.x;
    const int tx = tid % TX, ty = tid / TX;

    float acc[TM][TN];
#pragma unroll
    for (int i = 0; i < TM; i++)
#pragma unroll
        for (int j = 0; j < TN; j++) acc[i][j] = 0.f;

    for (int k0 = 0; k0 < K; k0 += BK) {
        for (int l = tid; l < BM * BK; l += NT) {
            int m = l / BK, kk = l % BK;
            As[kk][m] = A[(long long)(m0 + m) * lda + k0 + kk];
        }
        for (int l = tid; l < BK * BN; l += NT) {
            int kk = l / BN, n = l % BN;
            Bs[kk][n] = Bm[(long long)(k0 + kk) * ldb + n0 + n];
        }
        __syncthreads();
#pragma unroll
        for (int kk = 0; kk < BK; kk++) {
            float a[TM], bf[TN];
#pragma unroll
            for (int i = 0; i < TM; i++) a[i] = As[kk][ty * TM + i];
#pragma unroll
            for (int j = 0; j < TN; j++) bf[j] = Bs[kk][tx * TN + j];
#pragma unroll
            for (int i = 0; i < TM; i++)
#pragma unroll
                for (int j = 0; j < TN; j++) acc[i][j] += a[i] * bf[j];
        }
        __syncthreads();
    }

#pragma unroll
    for (int i = 0; i < TM; i++) {
        const int m = m0 + ty * TM + i;
#pragma unroll
        for (int j = 0; j < TN; j++) {
            const int n = n0 + tx * TN + j;
            float v = acc[i][j];
            if (colBias) v += colBias[n];
            if (resid)   v += resid[(long long)m * ldr + n];
            C[(long long)m * ldc + n] = v;
        }
    }
}

// ---------------------------------------------------------------------------
// Fused KS / cvec kernel: one warp per (b, n, s).
//   KS = kh + r (written back into g_kh)
//   cvec[b,n,s] = sum_h rwb[n,h]*kh + rrb[n,h]*r
// ---------------------------------------------------------------------------
__global__ void ks_cvec_kernel(const float* __restrict__ rwb,
                               const float* __restrict__ rrb)
{
    const int gw = (blockIdx.x * blockDim.x + threadIdx.x) >> 5;
    const int lane = threadIdx.x & 31;
    if (gw >= B_ * N_ * S_) return;
    const int s = gw % S_;
    const int n = (gw / S_) % N_;
    const int b = gw / (S_ * N_);

    const long long khOff = (long long)(b * S_ + s) * D_ + n * H_;
    const long long rOff  = (long long)s * D_ + n * H_;

    float acc = 0.f;
#pragma unroll
    for (int h = lane; h < H_; h += 32) {
        float kv = g_kh[khOff + h];
        float rv = g_r[rOff + h];
        g_kh[khOff + h] = kv + rv;
        acc += rwb[n * H_ + h] * kv + rrb[n * H_ + h] * rv;
    }
#pragma unroll
    for (int o = 16; o; o >>= 1) acc += __shfl_xor_sync(~0u, acc, o);
    if (lane == 0) g_cvec[(long long)(b * N_ + n) * S_ + s] = acc;
}

// ---------------------------------------------------------------------------
// Batched NT GEMM: scores[z][q][k] = norm*(qh . KS + cvec[k]) - BIG*mask[k]
// z = b*N + n. A rows: qh[b,:,n,:], B rows: KS[b,:,n,:] (lda = D).
// ---------------------------------------------------------------------------
__global__ void __launch_bounds__(256)
scores_nt_kernel(const int* __restrict__ mask)
{
    __shared__ float As[8][128];
    __shared__ float Bs[8][128];

    const int z = blockIdx.z;
    const int b = z >> 4, n = z & 15;
    const float* A  = g_qh + (long long)b * S_ * D_ + n * H_;
    const float* Bm = g_kh + (long long)b * S_ * D_ + n * H_;
    float* C = g_scores + (long long)z * S_ * S_;

    const int m0 = blockIdx.y * 128, n0 = blockIdx.x * 128;
    const int tid = threadIdx.x;
    const int tx = tid & 15, ty = tid >> 4;

    float acc[8][8];
#pragma unroll
    for (int i = 0; i < 8; i++)
#pragma unroll
        for (int j = 0; j < 8; j++) acc[i][j] = 0.f;

    for (int k0 = 0; k0 < H_; k0 += 8) {
        for (int l = tid; l < 1024; l += 256) {
            int m = l >> 3, kk = l & 7;
            As[kk][m] = A[(long long)(m0 + m) * D_ + k0 + kk];
        }
        for (int l = tid; l < 1024; l += 256) {
            int nn = l >> 3, kk = l & 7;
            Bs[kk][nn] = Bm[(long long)(n0 + nn) * D_ + k0 + kk];
        }
        __syncthreads();
#pragma unroll
        for (int kk = 0; kk < 8; kk++) {
            float a[8], bf[8];
#pragma unroll
            for (int i = 0; i < 8; i++) a[i] = As[kk][ty * 8 + i];
#pragma unroll
            for (int j = 0; j < 8; j++) bf[j] = Bs[kk][tx * 8 + j];
#pragma unroll
            for (int i = 0; i < 8; i++)
#pragma unroll
                for (int j = 0; j < 8; j++) acc[i][j] += a[i] * bf[j];
        }
        __syncthreads();
    }

    const float* cv = g_cvec + (long long)z * S_;
    const int*   mk = mask + b * S_;
#pragma unroll
    for (int i = 0; i < 8; i++) {
        const int m = m0 + ty * 8 + i;
#pragma unroll
        for (int j = 0; j < 8; j++) {
            const int nn = n0 + tx * 8 + j;
            C[(long long)m * S_ + nn] =
                NORM_ * (acc[i][j] + cv[nn]) - BIGC_ * (float)mk[nn];
        }
    }
}

// ---------------------------------------------------------------------------
// Row softmax over 1024 elements, in place. One block (256 thr) per row.
// ---------------------------------------------------------------------------
__global__ void __launch_bounds__(256) softmax_kernel()
{
    float* p = g_scores + (long long)blockIdx.x * S_;
    const int t = threadIdx.x;
    __shared__ float sred[8];

    float v[4];
    float mx = -3.0e38f;
#pragma unroll
    for (int i = 0; i < 4; i++) { v[i] = p[t + 256 * i]; mx = fmaxf(mx, v[i]); }
#pragma unroll
    for (int o = 16; o; o >>= 1) mx = fmaxf(mx, __shfl_xor_sync(~0u, mx, o));
    if ((t & 31) == 0) sred[t >> 5] = mx;
    __syncthreads();
    mx = sred[0];
#pragma unroll
    for (int i = 1; i < 8; i++) mx = fmaxf(mx, sred[i]);
    __syncthreads();

    float s = 0.f;
#pragma unroll
    for (int i = 0; i < 4; i++) { v[i] = __expf(v[i] - mx); s += v[i]; }
#pragma unroll
    for (int o = 16; o; o >>= 1) s += __shfl_xor_sync(~0u, s, o);
    if ((t & 31) == 0) sred[t >> 5] = s;
    __syncthreads();
    s = 0.f;
#pragma unroll
    for (int i = 0; i < 8; i++) s += sred[i];
    const float inv = 1.0f / s;
#pragma unroll
    for (int i = 0; i < 4; i++) p[t + 256 * i] = v[i] * inv;
}

// ---------------------------------------------------------------------------
// LayerNorm in place on d_out rows (1024 elems). One block per row.
// ---------------------------------------------------------------------------
__global__ void __launch_bounds__(256)
ln_kernel(float* __restrict__ x, const float* __restrict__ gamma,
          const float* __restrict__ beta)
{
    float* p = x + (long long)blockIdx.x * D_;
    const int t = threadIdx.x;
    __shared__ float sred[8];

    float v[4];
    float s = 0.f;
#pragma unroll
    for (int i = 0; i < 4; i++) { v[i] = p[t + 256 * i]; s += v[i]; }
#pragma unroll
    for (int o = 16; o; o >>= 1) s += __shfl_xor_sync(~0u, s, o);
    if ((t & 31) == 0) sred[t >> 5] = s;
    __syncthreads();
    s = 0.f;
#pragma unroll
    for (int i = 0; i < 8; i++) s += sred[i];
    const float mean = s * (1.0f / D_);
    __syncthreads();

    float vs = 0.f;
#pragma unroll
    for (int i = 0; i < 4; i++) { float d = v[i] - mean; vs += d * d; }
#pragma unroll
    for (int o = 16; o; o >>= 1) vs += __shfl_xor_sync(~0u, vs, o);
    if ((t & 31) == 0) sred[t >> 5] = vs;
    __syncthreads();
    vs = 0.f;
#pragma unroll
    for (int i = 0; i < 8; i++) vs += sred[i];
    const float rstd = rsqrtf(vs * (1.0f / D_) + LNEPS_);

#pragma unroll
    for (int i = 0; i < 4; i++) {
        const int col = t + 256 * i;
        p[col] = (v[i] - mean) * rstd * gamma[col] + beta[col];
    }
}

// ---------------------------------------------------------------------------
// Host launcher
// ---------------------------------------------------------------------------
extern "C" void kernel_launch(void* const* d_in, const int* in_sizes, int n_in,
                              void* d_out, int out_size)
{
    const float* q        = (const float*)d_in[0];
    const float* k        = (const float*)d_in[1];
    const float* v        = (const float*)d_in[2];
    const float* pos_enc  = (const float*)d_in[3];
    const int*   mask     = (const int*)  d_in[4];
    const float* q_w      = (const float*)d_in[5];
    const float* k_w      = (const float*)d_in[6];
    const float* k_b      = (const float*)d_in[7];
    const float* v_w      = (const float*)d_in[8];
    const float* v_b      = (const float*)d_in[9];
    const float* rwb      = (const float*)d_in[10];
    const float* rrb      = (const float*)d_in[11];
    const float* r_kernel = (const float*)d_in[12];
    const float* post_w   = (const float*)d_in[13];
    const float* post_b   = (const float*)d_in[14];
    const float* ln_g     = (const float*)d_in[15];
    const float* ln_b     = (const float*)d_in[16];
    float* out = (float*)d_out;

    void* p;
    cudaGetSymbolAddress(&p, g_qh);     float* qh = (float*)p;
    cudaGetSymbolAddress(&p, g_kh);     float* kh = (float*)p;
    cudaGetSymbolAddress(&p, g_vh);     float* vh = (float*)p;
    cudaGetSymbolAddress(&p, g_r);      float* rr = (float*)p;
    cudaGetSymbolAddress(&p, g_scores); float* sc = (float*)p;
    cudaGetSymbolAddress(&p, g_out);    float* ao = (float*)p;

    const int M = B_ * S_;  // 2048

    // 1-3. QKV projections: [2048,1024] x [1024,1024]
    {
        dim3 grid(D_ / 128, M / 128, 1);
        sgemm_nn_kernel<128, 128, 8, 8, 8><<<grid, 256>>>(
            q, q_w, qh, M, D_, D_, D_, D_, D_,
            1, 0, 0, 0, 0, 0, 0, nullptr, nullptr, 0);
        sgemm_nn_kernel<128, 128, 8, 8, 8><<<grid, 256>>>(
            k, k_w, kh, M, D_, D_, D_, D_, D_,
            1, 0, 0, 0, 0, 0, 0, k_b, nullptr, 0);
        sgemm_nn_kernel<128, 128, 8, 8, 8><<<grid, 256>>>(
            v, v_w, vh, M, D_, D_, D_, D_, D_,
            1, 0, 0, 0, 0, 0, 0, v_b, nullptr, 0);
    }

    // 4. r[s,n,h] = pos_enc[:1024] @ r_kernel[n]  (batched over n)
    {
        dim3 grid(1, S_ / 64, N_);
        sgemm_nn_kernel<64, 64, 16, 4, 4><<<grid, 256>>>(
            pos_enc, r_kernel, rr, S_, H_, D_, D_, H_, D_,
            N_,
            0, 0,                                  // A: shared
            0, (long long)D_ * H_,                 // B: + n*D*H
            0, (long long)H_,                      // C: + n*H
            nullptr, nullptr, 0);
    }

    // 5. KS = kh + r; cvec
    ks_cvec_kernel<<<(B_ * N_ * S_) / 8, 256>>>(rwb, rrb);

    // 6. scores (NT) with norm / cvec / mask epilogue
    {
        dim3 grid(S_ / 128, S_ / 128, B_ * N_);
        scores_nt_kernel<<<grid, 256>>>(mask);
    }

    // 7. softmax
    softmax_kernel<<<B_ * N_ * S_, 256>>>();

    // 8. out = P @ V  (batched over z = b*N+n)
    {
        dim3 grid(1, S_ / 64, B_ * N_);
        sgemm_nn_kernel<64, 64, 16, 4, 4><<<grid, 256>>>(
            sc, vh, ao, S_, H_, S_, S_, D_, D_,
            N_,
            (long long)N_ * S_ * S_, (long long)S_ * S_,  // A: z*S*S
            (long long)S_ * D_, (long long)H_,            // B: b*S*D + n*H
            (long long)S_ * D_, (long long)H_,            // C: b*S*D + n*H
            nullptr, nullptr, 0);
    }

    // 9. post GEMM + bias + residual -> d_out
    {
        dim3 grid(D_ / 128, M / 128, 1);
        sgemm_nn_kernel<128, 128, 8, 8, 8><<<grid, 256>>>(
            ao, post_w, out, M, D_, D_, D_, D_, D_,
            1, 0, 0, 0, 0, 0, 0, post_b, q, D_);
    }

    // 10. LayerNorm in place
    ln_kernel<<<M, 256>>>(out, ln_g, ln_b);
}

// round 5
// speedup vs baseline: 5.7323x; 5.7323x over previous
#include <cuda_runtime.h>
#include <math.h>
#include <stdint.h>

// Problem constants
constexpr int B_ = 2, S_ = 1024, D_ = 1024, N_ = 16, H_ = 64;
constexpr float NORM_ = 0.125f;       // 1/sqrt(64)
constexpr float BIGC_ = 1000000.0f;
constexpr float LNEPS_ = 1e-5f;

// Scratch (static device globals — no runtime allocation)
__device__ __align__(16) float g_qh[B_ * S_ * D_];
__device__ __align__(16) float g_kh[B_ * S_ * D_];          // becomes KS = kh + r
__device__ __align__(16) float g_vh[B_ * S_ * D_];
__device__ __align__(16) float g_r [S_ * D_];
__device__ __align__(16) float g_cvec[B_ * N_ * S_];
__device__ __align__(16) float g_scores[B_ * N_ * S_ * S_]; // 134 MB
__device__ __align__(16) float g_out[B_ * S_ * D_];

// ---------------------------------------------------------------------------
// tf32 helpers
// ---------------------------------------------------------------------------
__device__ __forceinline__ uint32_t f2tf(float x) {
    uint32_t r;
    asm("cvt.rna.tf32.f32 %0, %1;" : "=r"(r) : "f"(x));
    return r;
}

__device__ __forceinline__ void mma8(float* c, const uint32_t* a, const uint32_t* b) {
    asm volatile(
        "mma.sync.aligned.m16n8k8.row.col.f32.tf32.tf32.f32 "
        "{%0,%1,%2,%3},{%4,%5,%6,%7},{%8,%9},{%0,%1,%2,%3};\n"
        : "+f"(c[0]), "+f"(c[1]), "+f"(c[2]), "+f"(c[3])
        : "r"(a[0]), "r"(a[1]), "r"(a[2]), "r"(a[3]), "r"(b[0]), "r"(b[1]));
}

// ---------------------------------------------------------------------------
// Batched tf32 tensor-core GEMM.
//   C[M,N] = A[M,K] * op(B) ; BT=false: B is [K,N] row-major (NN)
//                             BT=true : B is [N,K] row-major (NT)
// Batch z: bo = z / nInner, bi = z % nInner; operand offset bo*Out + bi*In.
// EPI==0: optional colBias / resid.  EPI==1: scores epilogue
//   C = NORM_*(acc + cvec[z*S + col]) - BIGC_*mask[bo*S + col]
// Requires: M % BM == 0, N % BN == 0, K % 16 == 0.
// ---------------------------------------------------------------------------
template <int BM, int BN, int WMS, int WNS, bool BT, int EPI>
__global__ void __launch_bounds__(WMS * WNS * 32)
tgemm(const float* __restrict__ A, const float* __restrict__ Bm,
      float* __restrict__ C, int K, int lda, int ldb, int ldc,
      int nInner,
      long long aOut, long long aIn,
      long long bOut, long long bIn,
      long long cOut, long long cIn,
      const float* __restrict__ colBias,
      const float* __restrict__ resid, int ldr,
      const float* __restrict__ cvec, const int* __restrict__ mask)
{
    constexpr int NTHR = WMS * WNS * 32;
    constexpr int BKP  = 20;            // 16 + pad 4 -> conflict-free frag LDS
    constexpr int WTM  = BM / WMS, WTN = BN / WNS;
    constexpr int MT   = WTM / 16, NT2 = WTN / 8;
    constexpr int AV   = 4 * BM / NTHR;   // float4 loads per thread for A
    constexpr int BV   = 4 * BN / NTHR;   // per-thread B load groups

    __shared__ uint32_t As[2][BM][BKP];
    __shared__ uint32_t Bs[2][BN][BKP];

    const int z  = blockIdx.z;
    const int bo = z / nInner, bi = z % nInner;
    A  += bo * aOut + bi * aIn;
    Bm += bo * bOut + bi * bIn;
    C  += bo * cOut + bi * cIn;
    if (EPI == 1) { cvec += (long long)z * S_; mask += (long long)bo * S_; }

    const int m0 = blockIdx.y * BM, n0 = blockIdx.x * BN;
    const int tid = threadIdx.x, lane = tid & 31, wid = tid >> 5;
    const int g = lane >> 2, tig = lane & 3;
    const int wm = wid / WNS, wn = wid % WNS;

    float4 aSt[AV];
    float  bSt[BV][4];
    const int NK = K / 16;

    auto loadG = [&](int k0) {
#pragma unroll
        for (int i = 0; i < AV; i++) {
            int v = tid + i * NTHR; int row = v >> 2, c4 = v & 3;
            aSt[i] = *reinterpret_cast<const float4*>(
                A + (long long)(m0 + row) * lda + k0 + 4 * c4);
        }
        if constexpr (BT) {
#pragma unroll
            for (int i = 0; i < BV; i++) {
                int v = tid + i * NTHR; int row = v >> 2, c4 = v & 3;
                float4 t = *reinterpret_cast<const float4*>(
                    Bm + (long long)(n0 + row) * ldb + k0 + 4 * c4);
                bSt[i][0] = t.x; bSt[i][1] = t.y; bSt[i][2] = t.z; bSt[i][3] = t.w;
            }
        } else {
#pragma unroll
            for (int i = 0; i < BV; i++) {
                int n = tid % BN; int kb = tid / BN + i * (NTHR / BN);
#pragma unroll
                for (int j = 0; j < 4; j++)
                    bSt[i][j] = Bm[(long long)(k0 + kb * 4 + j) * ldb + n0 + n];
            }
        }
    };

    auto storeS = [&](int st) {
#pragma unroll
        for (int i = 0; i < AV; i++) {
            int v = tid + i * NTHR; int row = v >> 2, c4 = v & 3;
            uint32_t* p = &As[st][row][4 * c4];
            p[0] = f2tf(aSt[i].x); p[1] = f2tf(aSt[i].y);
            p[2] = f2tf(aSt[i].z); p[3] = f2tf(aSt[i].w);
        }
        if constexpr (BT) {
#pragma unroll
            for (int i = 0; i < BV; i++) {
                int v = tid + i * NTHR; int row = v >> 2, c4 = v & 3;
                uint32_t* p = &Bs[st][row][4 * c4];
#pragma unroll
                for (int j = 0; j < 4; j++) p[j] = f2tf(bSt[i][j]);
            }
        } else {
#pragma unroll
            for (int i = 0; i < BV; i++) {
                int n = tid % BN; int kb = tid / BN + i * (NTHR / BN);
                uint32_t* p = &Bs[st][n][4 * kb];
#pragma unroll
                for (int j = 0; j < 4; j++) p[j] = f2tf(bSt[i][j]);
            }
        }
    };

    float acc[MT][NT2][4];
#pragma unroll
    for (int mt = 0; mt < MT; mt++)
#pragma unroll
        for (int nt = 0; nt < NT2; nt++)
#pragma unroll
            for (int j = 0; j < 4; j++) acc[mt][nt][j] = 0.f;

    auto comp = [&](int st) {
#pragma unroll
        for (int kt = 0; kt < 2; kt++) {
            uint32_t af[MT][4], bf[NT2][2];
#pragma unroll
            for (int mt = 0; mt < MT; mt++) {
                int r0 = wm * WTM + mt * 16 + g;
                af[mt][0] = As[st][r0    ][kt * 8 + tig];
                af[mt][1] = As[st][r0 + 8][kt * 8 + tig];
                af[mt][2] = As[st][r0    ][kt * 8 + tig + 4];
                af[mt][3] = As[st][r0 + 8][kt * 8 + tig + 4];
            }
#pragma unroll
            for (int nt = 0; nt < NT2; nt++) {
                int c0 = wn * WTN + nt * 8 + g;
                bf[nt][0] = Bs[st][c0][kt * 8 + tig];
                bf[nt][1] = Bs[st][c0][kt * 8 + tig + 4];
            }
#pragma unroll
            for (int mt = 0; mt < MT; mt++)
#pragma unroll
                for (int nt = 0; nt < NT2; nt++)
                    mma8(acc[mt][nt], af[mt], bf[nt]);
        }
    };

    loadG(0); storeS(0); __syncthreads();
    int cur = 0;
    for (int it = 1; it <= NK; it++) {
        if (it < NK) loadG(it * 16);
        comp(cur);
        if (it < NK) storeS(cur ^ 1);
        __syncthreads();
        cur ^= 1;
    }

    // Epilogue
#pragma unroll
    for (int mt = 0; mt < MT; mt++) {
        int r0 = m0 + wm * WTM + mt * 16 + g;
#pragma unroll
        for (int nt = 0; nt < NT2; nt++) {
            int col = n0 + wn * WTN + nt * 8 + 2 * tig;
            float v0 = acc[mt][nt][0], v1 = acc[mt][nt][1];
            float v2 = acc[mt][nt][2], v3 = acc[mt][nt][3];
            if (EPI == 1) {
                float cv0 = cvec[col], cv1 = cvec[col + 1];
                float mk0 = BIGC_ * (float)mask[col];
                float mk1 = BIGC_ * (float)mask[col + 1];
                v0 = NORM_ * (v0 + cv0) - mk0; v1 = NORM_ * (v1 + cv1) - mk1;
                v2 = NORM_ * (v2 + cv0) - mk0; v3 = NORM_ * (v3 + cv1) - mk1;
            } else {
                if (colBias) {
                    float b0f = colBias[col], b1f = colBias[col + 1];
                    v0 += b0f; v1 += b1f; v2 += b0f; v3 += b1f;
                }
                if (resid) {
                    v0 += resid[(long long)r0 * ldr + col];
                    v1 += resid[(long long)r0 * ldr + col + 1];
                    v2 += resid[(long long)(r0 + 8) * ldr + col];
                    v3 += resid[(long long)(r0 + 8) * ldr + col + 1];
                }
            }
            *reinterpret_cast<float2*>(&C[(long long)r0 * ldc + col]) =
                make_float2(v0, v1);
            *reinterpret_cast<float2*>(&C[(long long)(r0 + 8) * ldc + col]) =
                make_float2(v2, v3);
        }
    }
}

// ---------------------------------------------------------------------------
// Fused KS / cvec kernel: one warp per (b, n, s).
//   KS = kh + r (in place in g_kh)
//   cvec[b,n,s] = sum_h rwb[n,h]*kh + rrb[n,h]*r
// ---------------------------------------------------------------------------
__global__ void ks_cvec_kernel(const float* __restrict__ rwb,
                               const float* __restrict__ rrb)
{
    const int gw = (blockIdx.x * blockDim.x + threadIdx.x) >> 5;
    const int lane = threadIdx.x & 31;
    if (gw >= B_ * N_ * S_) return;
    const int s = gw % S_;
    const int n = (gw / S_) % N_;
    const int b = gw / (S_ * N_);

    const long long khOff = (long long)(b * S_ + s) * D_ + n * H_;
    const long long rOff  = (long long)s * D_ + n * H_;

    float acc = 0.f;
#pragma unroll
    for (int h = lane; h < H_; h += 32) {
        float kv = g_kh[khOff + h];
        float rv = g_r[rOff + h];
        g_kh[khOff + h] = kv + rv;
        acc += rwb[n * H_ + h] * kv + rrb[n * H_ + h] * rv;
    }
#pragma unroll
    for (int o = 16; o; o >>= 1) acc += __shfl_xor_sync(~0u, acc, o);
    if (lane == 0) g_cvec[(long long)(b * N_ + n) * S_ + s] = acc;
}

// ---------------------------------------------------------------------------
// Row softmax over 1024 elements, in place. One block (256 thr) per row.
// ---------------------------------------------------------------------------
__global__ void __launch_bounds__(256) softmax_kernel()
{
    float* p = g_scores + (long long)blockIdx.x * S_;
    const int t = threadIdx.x;
    __shared__ float sred[8];

    float v[4];
    float mx = -3.0e38f;
#pragma unroll
    for (int i = 0; i < 4; i++) { v[i] = p[t + 256 * i]; mx = fmaxf(mx, v[i]); }
#pragma unroll
    for (int o = 16; o; o >>= 1) mx = fmaxf(mx, __shfl_xor_sync(~0u, mx, o));
    if ((t & 31) == 0) sred[t >> 5] = mx;
    __syncthreads();
    mx = sred[0];
#pragma unroll
    for (int i = 1; i < 8; i++) mx = fmaxf(mx, sred[i]);
    __syncthreads();

    float s = 0.f;
#pragma unroll
    for (int i = 0; i < 4; i++) { v[i] = __expf(v[i] - mx); s += v[i]; }
#pragma unroll
    for (int o = 16; o; o >>= 1) s += __shfl_xor_sync(~0u, s, o);
    if ((t & 31) == 0) sred[t >> 5] = s;
    __syncthreads();
    s = 0.f;
#pragma unroll
    for (int i = 0; i < 8; i++) s += sred[i];
    const float inv = 1.0f / s;
#pragma unroll
    for (int i = 0; i < 4; i++) p[t + 256 * i] = v[i] * inv;
}

// ---------------------------------------------------------------------------
// LayerNorm in place on d_out rows. One block (256 thr) per row.
// ---------------------------------------------------------------------------
__global__ void __launch_bounds__(256)
ln_kernel(float* __restrict__ x, const float* __restrict__ gamma,
          const float* __restrict__ beta)
{
    float* p = x + (long long)blockIdx.x * D_;
    const int t = threadIdx.x;
    __shared__ float sred[8];

    float v[4];
    float s = 0.f;
#pragma unroll
    for (int i = 0; i < 4; i++) { v[i] = p[t + 256 * i]; s += v[i]; }
#pragma unroll
    for (int o = 16; o; o >>= 1) s += __shfl_xor_sync(~0u, s, o);
    if ((t & 31) == 0) sred[t >> 5] = s;
    __syncthreads();
    s = 0.f;
#pragma unroll
    for (int i = 0; i < 8; i++) s += sred[i];
    const float mean = s * (1.0f / D_);
    __syncthreads();

    float vs = 0.f;
#pragma unroll
    for (int i = 0; i < 4; i++) { float d = v[i] - mean; vs += d * d; }
#pragma unroll
    for (int o = 16; o; o >>= 1) vs += __shfl_xor_sync(~0u, vs, o);
    if ((t & 31) == 0) sred[t >> 5] = vs;
    __syncthreads();
    vs = 0.f;
#pragma unroll
    for (int i = 0; i < 8; i++) vs += sred[i];
    const float rstd = rsqrtf(vs * (1.0f / D_) + LNEPS_);

#pragma unroll
    for (int i = 0; i < 4; i++) {
        const int col = t + 256 * i;
        p[col] = (v[i] - mean) * rstd * gamma[col] + beta[col];
    }
}

// ---------------------------------------------------------------------------
// Host launcher
// ---------------------------------------------------------------------------
extern "C" void kernel_launch(void* const* d_in, const int* in_sizes, int n_in,
                              void* d_out, int out_size)
{
    const float* q        = (const float*)d_in[0];
    const float* k        = (const float*)d_in[1];
    const float* v        = (const float*)d_in[2];
    const float* pos_enc  = (const float*)d_in[3];
    const int*   mask     = (const int*)  d_in[4];
    const float* q_w      = (const float*)d_in[5];
    const float* k_w      = (const float*)d_in[6];
    const float* k_b      = (const float*)d_in[7];
    const float* v_w      = (const float*)d_in[8];
    const float* v_b      = (const float*)d_in[9];
    const float* rwb      = (const float*)d_in[10];
    const float* rrb      = (const float*)d_in[11];
    const float* r_kernel = (const float*)d_in[12];
    const float* post_w   = (const float*)d_in[13];
    const float* post_b   = (const float*)d_in[14];
    const float* ln_g     = (const float*)d_in[15];
    const float* ln_b     = (const float*)d_in[16];
    float* out = (float*)d_out;

    void* p;
    cudaGetSymbolAddress(&p, g_qh);     float* qh = (float*)p;
    cudaGetSymbolAddress(&p, g_kh);     float* kh = (float*)p;
    cudaGetSymbolAddress(&p, g_vh);     float* vh = (float*)p;
    cudaGetSymbolAddress(&p, g_r);      float* rr = (float*)p;
    cudaGetSymbolAddress(&p, g_scores); float* sc = (float*)p;
    cudaGetSymbolAddress(&p, g_out);    float* ao = (float*)p;
    cudaGetSymbolAddress(&p, g_cvec);   float* cv = (float*)p;   // FIX: was host-side symbol

    const long long SD = (long long)S_ * D_;
    const long long SS = (long long)S_ * S_;

    // 1-3. QKV projections: [2048,1024] x [1024,1024] (NN, tf32)
    {
        dim3 grid(D_ / 64, (B_ * S_) / 128, 1);
        tgemm<128, 64, 4, 2, false, 0><<<grid, 256>>>(
            q, q_w, qh, D_, D_, D_, D_,
            1, 0, 0, 0, 0, 0, 0, nullptr, nullptr, 0, nullptr, nullptr);
        tgemm<128, 64, 4, 2, false, 0><<<grid, 256>>>(
            k, k_w, kh, D_, D_, D_, D_,
            1, 0, 0, 0, 0, 0, 0, k_b, nullptr, 0, nullptr, nullptr);
        tgemm<128, 64, 4, 2, false, 0><<<grid, 256>>>(
            v, v_w, vh, D_, D_, D_, D_,
            1, 0, 0, 0, 0, 0, 0, v_b, nullptr, 0, nullptr, nullptr);
    }

    // 4. r[s,n,h] = pos_enc[:1024] @ r_kernel[n]  (batched over n, NN)
    {
        dim3 grid(1, S_ / 64, N_);
        tgemm<64, 64, 2, 2, false, 0><<<grid, 128>>>(
            pos_enc, r_kernel, rr, D_, D_, H_, D_,
            N_,
            0, 0,
            0, (long long)D_ * H_,
            0, (long long)H_,
            nullptr, nullptr, 0, nullptr, nullptr);
    }

    // 5. KS = kh + r; cvec
    ks_cvec_kernel<<<(B_ * N_ * S_) / 8, 256>>>(rwb, rrb);

    // 6. scores = qh @ KS^T  (NT, batched over z=b*16+n) with fused epilogue
    {
        dim3 grid(S_ / 128, S_ / 128, B_ * N_);
        tgemm<128, 128, 2, 4, true, 1><<<grid, 256>>>(
            qh, kh, sc, H_, D_, D_, S_,
            N_,
            SD, (long long)H_,
            SD, (long long)H_,
            (long long)N_ * SS, SS,
            nullptr, nullptr, 0, cv, mask);
    }

    // 7. softmax
    softmax_kernel<<<B_ * N_ * S_, 256>>>();

    // 8. out = P @ V  (NN, batched over z)
    {
        dim3 grid(1, S_ / 64, B_ * N_);
        tgemm<64, 64, 2, 2, false, 0><<<grid, 128>>>(
            sc, vh, ao, S_, S_, D_, D_,
            N_,
            (long long)N_ * SS, SS,
            SD, (long long)H_,
            SD, (long long)H_,
            nullptr, nullptr, 0, nullptr, nullptr);
    }

    // 9. post GEMM + bias + residual -> d_out (NN)
    {
        dim3 grid(D_ / 64, (B_ * S_) / 128, 1);
        tgemm<128, 64, 4, 2, false, 0><<<grid, 256>>>(
            ao, post_w, out, D_, D_, D_, D_,
            1, 0, 0, 0, 0, 0, 0, post_b, q, D_, nullptr, nullptr);
    }

    // 10. LayerNorm in place
    ln_kernel<<<B_ * S_, 256>>>(out, ln_g, ln_b);
}

// round 6
// speedup vs baseline: 6.5805x; 1.1480x over previous
#include <cuda_runtime.h>
#include <math.h>
#include <stdint.h>

// Problem constants
constexpr int B_ = 2, S_ = 1024, D_ = 1024, N_ = 16, H_ = 64;
constexpr float NORM_ = 0.125f;       // 1/sqrt(64)
constexpr float BIGC_ = 1000000.0f;
constexpr float LNEPS_ = 1e-5f;

// Scratch (static device globals — no runtime allocation)
__device__ __align__(16) float g_qh[B_ * S_ * D_];
__device__ __align__(16) float g_kh[B_ * S_ * D_];          // becomes KS = kh + r
__device__ __align__(16) float g_vh[B_ * S_ * D_];
__device__ __align__(16) float g_r [S_ * D_];
__device__ __align__(16) float g_cvec[B_ * N_ * S_];
__device__ __align__(16) float g_out[B_ * S_ * D_];

// ---------------------------------------------------------------------------
// tf32 helpers
// ---------------------------------------------------------------------------
__device__ __forceinline__ uint32_t f2tf(float x) {
    uint32_t r;
    asm("cvt.rna.tf32.f32 %0, %1;" : "=r"(r) : "f"(x));
    return r;
}

__device__ __forceinline__ void mma8(float* c, const uint32_t* a, const uint32_t* b) {
    asm volatile(
        "mma.sync.aligned.m16n8k8.row.col.f32.tf32.tf32.f32 "
        "{%0,%1,%2,%3},{%4,%5,%6,%7},{%8,%9},{%0,%1,%2,%3};\n"
        : "+f"(c[0]), "+f"(c[1]), "+f"(c[2]), "+f"(c[3])
        : "r"(a[0]), "r"(a[1]), "r"(a[2]), "r"(a[3]), "r"(b[0]), "r"(b[1]));
}

// ---------------------------------------------------------------------------
// Batched tf32 tensor-core GEMM (unchanged from round 5).
// ---------------------------------------------------------------------------
template <int BM, int BN, int WMS, int WNS, bool BT, int EPI>
__global__ void __launch_bounds__(WMS * WNS * 32)
tgemm(const float* __restrict__ A, const float* __restrict__ Bm,
      float* __restrict__ C, int K, int lda, int ldb, int ldc,
      int nInner,
      long long aOut, long long aIn,
      long long bOut, long long bIn,
      long long cOut, long long cIn,
      const float* __restrict__ colBias,
      const float* __restrict__ resid, int ldr,
      const float* __restrict__ cvec, const int* __restrict__ mask)
{
    constexpr int NTHR = WMS * WNS * 32;
    constexpr int BKP  = 20;
    constexpr int WTM  = BM / WMS, WTN = BN / WNS;
    constexpr int MT   = WTM / 16, NT2 = WTN / 8;
    constexpr int AV   = 4 * BM / NTHR;
    constexpr int BV   = 4 * BN / NTHR;

    __shared__ uint32_t As[2][BM][BKP];
    __shared__ uint32_t Bs[2][BN][BKP];

    const int z  = blockIdx.z;
    const int bo = z / nInner, bi = z % nInner;
    A  += bo * aOut + bi * aIn;
    Bm += bo * bOut + bi * bIn;
    C  += bo * cOut + bi * cIn;
    if (EPI == 1) { cvec += (long long)z * S_; mask += (long long)bo * S_; }

    const int m0 = blockIdx.y * BM, n0 = blockIdx.x * BN;
    const int tid = threadIdx.x, lane = tid & 31, wid = tid >> 5;
    const int g = lane >> 2, tig = lane & 3;
    const int wm = wid / WNS, wn = wid % WNS;

    float4 aSt[AV];
    float  bSt[BV][4];
    const int NK = K / 16;

    auto loadG = [&](int k0) {
#pragma unroll
        for (int i = 0; i < AV; i++) {
            int v = tid + i * NTHR; int row = v >> 2, c4 = v & 3;
            aSt[i] = *reinterpret_cast<const float4*>(
                A + (long long)(m0 + row) * lda + k0 + 4 * c4);
        }
        if constexpr (BT) {
#pragma unroll
            for (int i = 0; i < BV; i++) {
                int v = tid + i * NTHR; int row = v >> 2, c4 = v & 3;
                float4 t = *reinterpret_cast<const float4*>(
                    Bm + (long long)(n0 + row) * ldb + k0 + 4 * c4);
                bSt[i][0] = t.x; bSt[i][1] = t.y; bSt[i][2] = t.z; bSt[i][3] = t.w;
            }
        } else {
#pragma unroll
            for (int i = 0; i < BV; i++) {
                int n = tid % BN; int kb = tid / BN + i * (NTHR / BN);
#pragma unroll
                for (int j = 0; j < 4; j++)
                    bSt[i][j] = Bm[(long long)(k0 + kb * 4 + j) * ldb + n0 + n];
            }
        }
    };

    auto storeS = [&](int st) {
#pragma unroll
        for (int i = 0; i < AV; i++) {
            int v = tid + i * NTHR; int row = v >> 2, c4 = v & 3;
            uint32_t* p = &As[st][row][4 * c4];
            p[0] = f2tf(aSt[i].x); p[1] = f2tf(aSt[i].y);
            p[2] = f2tf(aSt[i].z); p[3] = f2tf(aSt[i].w);
        }
        if constexpr (BT) {
#pragma unroll
            for (int i = 0; i < BV; i++) {
                int v = tid + i * NTHR; int row = v >> 2, c4 = v & 3;
                uint32_t* p = &Bs[st][row][4 * c4];
#pragma unroll
                for (int j = 0; j < 4; j++) p[j] = f2tf(bSt[i][j]);
            }
        } else {
#pragma unroll
            for (int i = 0; i < BV; i++) {
                int n = tid % BN; int kb = tid / BN + i * (NTHR / BN);
                uint32_t* p = &Bs[st][n][4 * kb];
#pragma unroll
                for (int j = 0; j < 4; j++) p[j] = f2tf(bSt[i][j]);
            }
        }
    };

    float acc[MT][NT2][4];
#pragma unroll
    for (int mt = 0; mt < MT; mt++)
#pragma unroll
        for (int nt = 0; nt < NT2; nt++)
#pragma unroll
            for (int j = 0; j < 4; j++) acc[mt][nt][j] = 0.f;

    auto comp = [&](int st) {
#pragma unroll
        for (int kt = 0; kt < 2; kt++) {
            uint32_t af[MT][4], bf[NT2][2];
#pragma unroll
            for (int mt = 0; mt < MT; mt++) {
                int r0 = wm * WTM + mt * 16 + g;
                af[mt][0] = As[st][r0    ][kt * 8 + tig];
                af[mt][1] = As[st][r0 + 8][kt * 8 + tig];
                af[mt][2] = As[st][r0    ][kt * 8 + tig + 4];
                af[mt][3] = As[st][r0 + 8][kt * 8 + tig + 4];
            }
#pragma unroll
            for (int nt = 0; nt < NT2; nt++) {
                int c0 = wn * WTN + nt * 8 + g;
                bf[nt][0] = Bs[st][c0][kt * 8 + tig];
                bf[nt][1] = Bs[st][c0][kt * 8 + tig + 4];
            }
#pragma unroll
            for (int mt = 0; mt < MT; mt++)
#pragma unroll
                for (int nt = 0; nt < NT2; nt++)
                    mma8(acc[mt][nt], af[mt], bf[nt]);
        }
    };

    loadG(0); storeS(0); __syncthreads();
    int cur = 0;
    for (int it = 1; it <= NK; it++) {
        if (it < NK) loadG(it * 16);
        comp(cur);
        if (it < NK) storeS(cur ^ 1);
        __syncthreads();
        cur ^= 1;
    }

#pragma unroll
    for (int mt = 0; mt < MT; mt++) {
        int r0 = m0 + wm * WTM + mt * 16 + g;
#pragma unroll
        for (int nt = 0; nt < NT2; nt++) {
            int col = n0 + wn * WTN + nt * 8 + 2 * tig;
            float v0 = acc[mt][nt][0], v1 = acc[mt][nt][1];
            float v2 = acc[mt][nt][2], v3 = acc[mt][nt][3];
            if (EPI == 1) {
                float cv0 = cvec[col], cv1 = cvec[col + 1];
                float mk0 = BIGC_ * (float)mask[col];
                float mk1 = BIGC_ * (float)mask[col + 1];
                v0 = NORM_ * (v0 + cv0) - mk0; v1 = NORM_ * (v1 + cv1) - mk1;
                v2 = NORM_ * (v2 + cv0) - mk0; v3 = NORM_ * (v3 + cv1) - mk1;
            } else {
                if (colBias) {
                    float b0f = colBias[col], b1f = colBias[col + 1];
                    v0 += b0f; v1 += b1f; v2 += b0f; v3 += b1f;
                }
                if (resid) {
                    v0 += resid[(long long)r0 * ldr + col];
                    v1 += resid[(long long)r0 * ldr + col + 1];
                    v2 += resid[(long long)(r0 + 8) * ldr + col];
                    v3 += resid[(long long)(r0 + 8) * ldr + col + 1];
                }
            }
            *reinterpret_cast<float2*>(&C[(long long)r0 * ldc + col]) =
                make_float2(v0, v1);
            *reinterpret_cast<float2*>(&C[(long long)(r0 + 8) * ldc + col]) =
                make_float2(v2, v3);
        }
    }
}

// ---------------------------------------------------------------------------
// Fused KS / cvec kernel (unchanged).
// ---------------------------------------------------------------------------
__global__ void ks_cvec_kernel(const float* __restrict__ rwb,
                               const float* __restrict__ rrb)
{
    const int gw = (blockIdx.x * blockDim.x + threadIdx.x) >> 5;
    const int lane = threadIdx.x & 31;
    if (gw >= B_ * N_ * S_) return;
    const int s = gw % S_;
    const int n = (gw / S_) % N_;
    const int b = gw / (S_ * N_);

    const long long khOff = (long long)(b * S_ + s) * D_ + n * H_;
    const long long rOff  = (long long)s * D_ + n * H_;

    float acc = 0.f;
#pragma unroll
    for (int h = lane; h < H_; h += 32) {
        float kv = g_kh[khOff + h];
        float rv = g_r[rOff + h];
        g_kh[khOff + h] = kv + rv;
        acc += rwb[n * H_ + h] * kv + rrb[n * H_ + h] * rv;
    }
#pragma unroll
    for (int o = 16; o; o >>= 1) acc += __shfl_xor_sync(~0u, acc, o);
    if (lane == 0) g_cvec[(long long)(b * N_ + n) * S_ + s] = acc;
}

// ---------------------------------------------------------------------------
// Fused flash attention: scores + softmax + P@V in one kernel.
// Grid: (S/64 q-tiles, B*N). 128 threads (4 warps), warp w owns q-rows
// [w*16, w*16+16). Per K-tile of 128 keys:
//   S = Q @ KS^T (tf32 mma), s = NORM*acc + (NORM*cvec - BIG*mask)
//   online softmax (running max/sum), P -> smem (aliases K buffer) -> P@V.
// Output: g_out[(b*S+q)*D + n*H + h], already softmax-normalized.
// ---------------------------------------------------------------------------
constexpr int FBQ = 64;     // q rows per CTA
constexpr int FBK = 128;    // keys per tile
constexpr int FQS = 68;     // Q smem stride
constexpr int FKS = 68;     // K smem stride
constexpr int FVS = 68;     // V smem stride
constexpr int FPS = 132;    // P smem stride
constexpr int FKP_WORDS = FBK * FKS;                // 8704 > 64*132=8448
constexpr int FSMEM_WORDS = FBQ * FQS + FKP_WORDS + FBK * FVS + FBK;
constexpr int FSMEM_BYTES = FSMEM_WORDS * 4;        // 87552

__global__ void __launch_bounds__(128) flash_kernel(const int* __restrict__ mask)
{
    extern __shared__ float sm[];
    float* Qs   = sm;                       // [64][68] tf32
    float* KP   = Qs + FBQ * FQS;           // K tile [128][68] / P tile [64][132]
    float* Vs   = KP + FKP_WORDS;           // [128][68] tf32
    float* sAdd = Vs + FBK * FVS;           // [128]

    const int z = blockIdx.y;
    const int b = z >> 4, n = z & 15;
    const int q0 = blockIdx.x * FBQ;
    const int tid = threadIdx.x, lane = tid & 31, w = tid >> 5;
    const int g = lane >> 2, tig = lane & 3;
    const int r0 = w * 16 + g;

    const float* Qg = g_qh + (long long)b * S_ * D_ + n * H_;
    const float* Kg = g_kh + (long long)b * S_ * D_ + n * H_;
    const float* Vg = g_vh + (long long)b * S_ * D_ + n * H_;
    const float* cv = g_cvec + (long long)z * S_;
    const int*   mk = mask + b * S_;

    // Load Q tile (64 x 64) as tf32
#pragma unroll
    for (int i = 0; i < 8; i++) {
        int v = tid + i * 128;              // 64 rows * 16 float4
        int row = v >> 4, c4 = v & 15;
        float4 t = *reinterpret_cast<const float4*>(
            Qg + (long long)(q0 + row) * D_ + 4 * c4);
        float* p = Qs + row * FQS + 4 * c4;
        p[0] = __uint_as_float(f2tf(t.x)); p[1] = __uint_as_float(f2tf(t.y));
        p[2] = __uint_as_float(f2tf(t.z)); p[3] = __uint_as_float(f2tf(t.w));
    }

    float Oa[8][4];
#pragma unroll
    for (int i = 0; i < 8; i++)
#pragma unroll
        for (int j = 0; j < 4; j++) Oa[i][j] = 0.f;
    float m0r = -3.0e38f, m1r = -3.0e38f, l0r = 0.f, l1r = 0.f;

    for (int kt = 0; kt < S_ / FBK; kt++) {
        __syncthreads();   // prior-tile P/V reads done; Q store done (iter 0)
        const int kb = kt * FBK;
#pragma unroll
        for (int i = 0; i < 16; i++) {
            int v = tid + i * 128;          // 128 rows * 16 float4
            int row = v >> 4, c4 = v & 15;
            float4 t = *reinterpret_cast<const float4*>(
                Kg + (long long)(kb + row) * D_ + 4 * c4);
            float* p = KP + row * FKS + 4 * c4;
            p[0] = __uint_as_float(f2tf(t.x)); p[1] = __uint_as_float(f2tf(t.y));
            p[2] = __uint_as_float(f2tf(t.z)); p[3] = __uint_as_float(f2tf(t.w));
            float4 u = *reinterpret_cast<const float4*>(
                Vg + (long long)(kb + row) * D_ + 4 * c4);
            float* pv = Vs + row * FVS + 4 * c4;
            pv[0] = __uint_as_float(f2tf(u.x)); pv[1] = __uint_as_float(f2tf(u.y));
            pv[2] = __uint_as_float(f2tf(u.z)); pv[3] = __uint_as_float(f2tf(u.w));
        }
        sAdd[tid] = NORM_ * cv[kb + tid] - BIGC_ * (float)mk[kb + tid];
        __syncthreads();

        // S = Q @ K^T : per-warp 16 x 128
        float Sa[16][4];
#pragma unroll
        for (int i = 0; i < 16; i++)
#pragma unroll
            for (int j = 0; j < 4; j++) Sa[i][j] = 0.f;
#pragma unroll
        for (int ks = 0; ks < 8; ks++) {
            uint32_t a[4];
            a[0] = __float_as_uint(Qs[ r0      * FQS + ks * 8 + tig]);
            a[1] = __float_as_uint(Qs[(r0 + 8) * FQS + ks * 8 + tig]);
            a[2] = __float_as_uint(Qs[ r0      * FQS + ks * 8 + tig + 4]);
            a[3] = __float_as_uint(Qs[(r0 + 8) * FQS + ks * 8 + tig + 4]);
#pragma unroll
            for (int nt = 0; nt < 16; nt++) {
                uint32_t bfr[2];
                bfr[0] = __float_as_uint(KP[(nt * 8 + g) * FKS + ks * 8 + tig]);
                bfr[1] = __float_as_uint(KP[(nt * 8 + g) * FKS + ks * 8 + tig + 4]);
                mma8(Sa[nt], a, bfr);
            }
        }
        __syncthreads();   // all warps finished reading K from KP

        // Epilogue + online softmax
        float tm0 = -3.0e38f, tm1 = -3.0e38f;
#pragma unroll
        for (int nt = 0; nt < 16; nt++) {
            int c = nt * 8 + 2 * tig;
            float a0 = sAdd[c], a1 = sAdd[c + 1];
            Sa[nt][0] = NORM_ * Sa[nt][0] + a0;
            Sa[nt][1] = NORM_ * Sa[nt][1] + a1;
            Sa[nt][2] = NORM_ * Sa[nt][2] + a0;
            Sa[nt][3] = NORM_ * Sa[nt][3] + a1;
            tm0 = fmaxf(tm0, fmaxf(Sa[nt][0], Sa[nt][1]));
            tm1 = fmaxf(tm1, fmaxf(Sa[nt][2], Sa[nt][3]));
        }
        tm0 = fmaxf(tm0, __shfl_xor_sync(~0u, tm0, 1));
        tm0 = fmaxf(tm0, __shfl_xor_sync(~0u, tm0, 2));
        tm1 = fmaxf(tm1, __shfl_xor_sync(~0u, tm1, 1));
        tm1 = fmaxf(tm1, __shfl_xor_sync(~0u, tm1, 2));
        float mn0 = fmaxf(m0r, tm0), mn1 = fmaxf(m1r, tm1);
        float sc0 = __expf(m0r - mn0), sc1 = __expf(m1r - mn1);
        m0r = mn0; m1r = mn1;

        float rs0 = 0.f, rs1 = 0.f;
#pragma unroll
        for (int nt = 0; nt < 16; nt++) {
            int c = nt * 8 + 2 * tig;
            float p0 = __expf(Sa[nt][0] - mn0);
            float p1 = __expf(Sa[nt][1] - mn0);
            float p2 = __expf(Sa[nt][2] - mn1);
            float p3 = __expf(Sa[nt][3] - mn1);
            rs0 += p0 + p1; rs1 += p2 + p3;
            KP[ r0      * FPS + c    ] = __uint_as_float(f2tf(p0));
            KP[ r0      * FPS + c + 1] = __uint_as_float(f2tf(p1));
            KP[(r0 + 8) * FPS + c    ] = __uint_as_float(f2tf(p2));
            KP[(r0 + 8) * FPS + c + 1] = __uint_as_float(f2tf(p3));
        }
        rs0 += __shfl_xor_sync(~0u, rs0, 1); rs0 += __shfl_xor_sync(~0u, rs0, 2);
        rs1 += __shfl_xor_sync(~0u, rs1, 1); rs1 += __shfl_xor_sync(~0u, rs1, 2);
        l0r = l0r * sc0 + rs0;
        l1r = l1r * sc1 + rs1;
#pragma unroll
        for (int nt = 0; nt < 8; nt++) {
            Oa[nt][0] *= sc0; Oa[nt][1] *= sc0;
            Oa[nt][2] *= sc1; Oa[nt][3] *= sc1;
        }
        __syncwarp();      // P visible within warp (A-frags are own 16 rows)

        // O += P(16x128) @ V(128x64)
#pragma unroll
        for (int ks = 0; ks < 16; ks++) {
            uint32_t a[4];
            a[0] = __float_as_uint(KP[ r0      * FPS + ks * 8 + tig]);
            a[1] = __float_as_uint(KP[(r0 + 8) * FPS + ks * 8 + tig]);
            a[2] = __float_as_uint(KP[ r0      * FPS + ks * 8 + tig + 4]);
            a[3] = __float_as_uint(KP[(r0 + 8) * FPS + ks * 8 + tig + 4]);
#pragma unroll
            for (int nt = 0; nt < 8; nt++) {
                uint32_t bfr[2];
                bfr[0] = __float_as_uint(Vs[(ks * 8 + tig    ) * FVS + nt * 8 + g]);
                bfr[1] = __float_as_uint(Vs[(ks * 8 + tig + 4) * FVS + nt * 8 + g]);
                mma8(Oa[nt], a, bfr);
            }
        }
    }

    // Normalize and write out
    const float inv0 = 1.0f / l0r, inv1 = 1.0f / l1r;
    float* Og = g_out + (long long)b * S_ * D_ + n * H_;
#pragma unroll
    for (int nt = 0; nt < 8; nt++) {
        int col = nt * 8 + 2 * tig;
        *reinterpret_cast<float2*>(
            Og + (long long)(q0 + r0) * D_ + col) =
            make_float2(Oa[nt][0] * inv0, Oa[nt][1] * inv0);
        *reinterpret_cast<float2*>(
            Og + (long long)(q0 + r0 + 8) * D_ + col) =
            make_float2(Oa[nt][2] * inv1, Oa[nt][3] * inv1);
    }
}

// ---------------------------------------------------------------------------
// LayerNorm in place on d_out rows. One block (256 thr) per row.
// ---------------------------------------------------------------------------
__global__ void __launch_bounds__(256)
ln_kernel(float* __restrict__ x, const float* __restrict__ gamma,
          const float* __restrict__ beta)
{
    float* p = x + (long long)blockIdx.x * D_;
    const int t = threadIdx.x;
    __shared__ float sred[8];

    float v[4];
    float s = 0.f;
#pragma unroll
    for (int i = 0; i < 4; i++) { v[i] = p[t + 256 * i]; s += v[i]; }
#pragma unroll
    for (int o = 16; o; o >>= 1) s += __shfl_xor_sync(~0u, s, o);
    if ((t & 31) == 0) sred[t >> 5] = s;
    __syncthreads();
    s = 0.f;
#pragma unroll
    for (int i = 0; i < 8; i++) s += sred[i];
    const float mean = s * (1.0f / D_);
    __syncthreads();

    float vs = 0.f;
#pragma unroll
    for (int i = 0; i < 4; i++) { float d = v[i] - mean; vs += d * d; }
#pragma unroll
    for (int o = 16; o; o >>= 1) vs += __shfl_xor_sync(~0u, vs, o);
    if ((t & 31) == 0) sred[t >> 5] = vs;
    __syncthreads();
    vs = 0.f;
#pragma unroll
    for (int i = 0; i < 8; i++) vs += sred[i];
    const float rstd = rsqrtf(vs * (1.0f / D_) + LNEPS_);

#pragma unroll
    for (int i = 0; i < 4; i++) {
        const int col = t + 256 * i;
        p[col] = (v[i] - mean) * rstd * gamma[col] + beta[col];
    }
}

// ---------------------------------------------------------------------------
// Host launcher
// ---------------------------------------------------------------------------
extern "C" void kernel_launch(void* const* d_in, const int* in_sizes, int n_in,
                              void* d_out, int out_size)
{
    const float* q        = (const float*)d_in[0];
    const float* k        = (const float*)d_in[1];
    const float* v        = (const float*)d_in[2];
    const float* pos_enc  = (const float*)d_in[3];
    const int*   mask     = (const int*)  d_in[4];
    const float* q_w      = (const float*)d_in[5];
    const float* k_w      = (const float*)d_in[6];
    const float* k_b      = (const float*)d_in[7];
    const float* v_w      = (const float*)d_in[8];
    const float* v_b      = (const float*)d_in[9];
    const float* rwb      = (const float*)d_in[10];
    const float* rrb      = (const float*)d_in[11];
    const float* r_kernel = (const float*)d_in[12];
    const float* post_w   = (const float*)d_in[13];
    const float* post_b   = (const float*)d_in[14];
    const float* ln_g     = (const float*)d_in[15];
    const float* ln_b     = (const float*)d_in[16];
    float* out = (float*)d_out;

    void* p;
    cudaGetSymbolAddress(&p, g_qh);     float* qh = (float*)p;
    cudaGetSymbolAddress(&p, g_kh);     float* kh = (float*)p;
    cudaGetSymbolAddress(&p, g_vh);     float* vh = (float*)p;
    cudaGetSymbolAddress(&p, g_r);      float* rr = (float*)p;
    cudaGetSymbolAddress(&p, g_out);    float* ao = (float*)p;

    // 1-3. QKV projections: [2048,1024] x [1024,1024] (NN, tf32)
    {
        dim3 grid(D_ / 64, (B_ * S_) / 128, 1);
        tgemm<128, 64, 4, 2, false, 0><<<grid, 256>>>(
            q, q_w, qh, D_, D_, D_, D_,
            1, 0, 0, 0, 0, 0, 0, nullptr, nullptr, 0, nullptr, nullptr);
        tgemm<128, 64, 4, 2, false, 0><<<grid, 256>>>(
            k, k_w, kh, D_, D_, D_, D_,
            1, 0, 0, 0, 0, 0, 0, k_b, nullptr, 0, nullptr, nullptr);
        tgemm<128, 64, 4, 2, false, 0><<<grid, 256>>>(
            v, v_w, vh, D_, D_, D_, D_,
            1, 0, 0, 0, 0, 0, 0, v_b, nullptr, 0, nullptr, nullptr);
    }

    // 4. r[s,n,h] = pos_enc[:1024] @ r_kernel[n]  (batched over n, NN)
    {
        dim3 grid(1, S_ / 64, N_);
        tgemm<64, 64, 2, 2, false, 0><<<grid, 128>>>(
            pos_enc, r_kernel, rr, D_, D_, H_, D_,
            N_,
            0, 0,
            0, (long long)D_ * H_,
            0, (long long)H_,
            nullptr, nullptr, 0, nullptr, nullptr);
    }

    // 5. KS = kh + r; cvec
    ks_cvec_kernel<<<(B_ * N_ * S_) / 8, 256>>>(rwb, rrb);

    // 6-8. Fused flash attention (scores + softmax + P@V) -> g_out
    {
        cudaFuncSetAttribute(flash_kernel,
                             cudaFuncAttributeMaxDynamicSharedMemorySize,
                             FSMEM_BYTES);
        dim3 grid(S_ / FBQ, B_ * N_);
        flash_kernel<<<grid, 128, FSMEM_BYTES>>>(mask);
    }

    // 9. post GEMM + bias + residual -> d_out (NN)
    {
        dim3 grid(D_ / 64, (B_ * S_) / 128, 1);
        tgemm<128, 64, 4, 2, false, 0><<<grid, 256>>>(
            ao, post_w, out, D_, D_, D_, D_,
            1, 0, 0, 0, 0, 0, 0, post_b, q, D_, nullptr, nullptr);
    }

    // 10. LayerNorm in place
    ln_kernel<<<B_ * S_, 256>>>(out, ln_g, ln_b);
}

// round 7
// speedup vs baseline: 7.7271x; 1.1742x over previous
#include <cuda_runtime.h>
#include <math.h>
#include <stdint.h>

// Problem constants
constexpr int B_ = 2, S_ = 1024, D_ = 1024, N_ = 16, H_ = 64;
constexpr float NORM_ = 0.125f;       // 1/sqrt(64)
constexpr float BIGC_ = 1000000.0f;
constexpr float LNEPS_ = 1e-5f;

// Scratch (static device globals — no runtime allocation)
__device__ __align__(16) float g_qh[B_ * S_ * D_];
__device__ __align__(16) float g_kh[B_ * S_ * D_];          // becomes KS = kh + r
__device__ __align__(16) float g_vh[B_ * S_ * D_];
__device__ __align__(16) float g_r [S_ * D_];
__device__ __align__(16) float g_rw[D_ * D_];               // r_kernel transposed [D, N*H]
__device__ __align__(16) float g_cvec[B_ * N_ * S_];
__device__ __align__(16) float g_out[B_ * S_ * D_];

// ---------------------------------------------------------------------------
// tf32 helpers
// ---------------------------------------------------------------------------
__device__ __forceinline__ uint32_t f2tf(float x) {
    uint32_t r;
    asm("cvt.rna.tf32.f32 %0, %1;" : "=r"(r) : "f"(x));
    return r;
}

__device__ __forceinline__ void mma8(float* c, const uint32_t* a, const uint32_t* b) {
    asm volatile(
        "mma.sync.aligned.m16n8k8.row.col.f32.tf32.tf32.f32 "
        "{%0,%1,%2,%3},{%4,%5,%6,%7},{%8,%9},{%0,%1,%2,%3};\n"
        : "+f"(c[0]), "+f"(c[1]), "+f"(c[2]), "+f"(c[3])
        : "r"(a[0]), "r"(a[1]), "r"(a[2]), "r"(a[3]), "r"(b[0]), "r"(b[1]));
}

// ---------------------------------------------------------------------------
// r_kernel transpose: [N, D, H] -> g_rw [D, N*H]. One thread per (d, n),
// copies H=64 contiguous floats (16 float4).
// ---------------------------------------------------------------------------
__global__ void rk_transpose(const float* __restrict__ rk)
{
    const int idx = blockIdx.x * blockDim.x + threadIdx.x;   // 0 .. 16383
    const int d = idx >> 4, n = idx & 15;
    const float4* src = reinterpret_cast<const float4*>(
        rk + ((long long)n * D_ + d) * H_);
    float4* dst = reinterpret_cast<float4*>(g_rw + (long long)d * D_ + n * H_);
#pragma unroll
    for (int i = 0; i < 16; i++) dst[i] = src[i];
}

// ---------------------------------------------------------------------------
// Multi-batch NN tf32 GEMM: one launch covers several independent GEMMs that
// share K / ld's / tile config. blockIdx.z selects {A, B, bias, C, M}.
// Blocks with m0 >= M exit immediately (ragged M support).
// ---------------------------------------------------------------------------
struct GemmBatch {
    const float* A;
    const float* Bm;
    const float* bias;
    float*       C;
    int          M;
};
struct GemmBatch4 { GemmBatch b[4]; };

template <int BM, int BN, int WMS, int WNS>
__global__ void __launch_bounds__(WMS * WNS * 32)
tgemm_multi(GemmBatch4 bs, int K, int lda, int ldb, int ldc)
{
    constexpr int NTHR = WMS * WNS * 32;
    constexpr int BKP  = 20;
    constexpr int WTM  = BM / WMS, WTN = BN / WNS;
    constexpr int MT   = WTM / 16, NT2 = WTN / 8;
    constexpr int AV   = 4 * BM / NTHR;
    constexpr int BV   = 4 * BN / NTHR;

    const GemmBatch P = bs.b[blockIdx.z];
    const int m0 = blockIdx.y * BM, n0 = blockIdx.x * BN;
    if (m0 >= P.M) return;

    __shared__ uint32_t As[2][BM][BKP];
    __shared__ uint32_t Bs[2][BN][BKP];

    const float* A  = P.A;
    const float* Bm = P.Bm;
    float* C = P.C;

    const int tid = threadIdx.x, lane = tid & 31, wid = tid >> 5;
    const int g = lane >> 2, tig = lane & 3;
    const int wm = wid / WNS, wn = wid % WNS;

    float4 aSt[AV];
    float  bSt[BV][4];
    const int NK = K / 16;

    auto loadG = [&](int k0) {
#pragma unroll
        for (int i = 0; i < AV; i++) {
            int v = tid + i * NTHR; int row = v >> 2, c4 = v & 3;
            aSt[i] = *reinterpret_cast<const float4*>(
                A + (long long)(m0 + row) * lda + k0 + 4 * c4);
        }
#pragma unroll
        for (int i = 0; i < BV; i++) {
            int n = tid % BN; int kb = tid / BN + i * (NTHR / BN);
#pragma unroll
            for (int j = 0; j < 4; j++)
                bSt[i][j] = Bm[(long long)(k0 + kb * 4 + j) * ldb + n0 + n];
        }
    };

    auto storeS = [&](int st) {
#pragma unroll
        for (int i = 0; i < AV; i++) {
            int v = tid + i * NTHR; int row = v >> 2, c4 = v & 3;
            uint32_t* p = &As[st][row][4 * c4];
            p[0] = f2tf(aSt[i].x); p[1] = f2tf(aSt[i].y);
            p[2] = f2tf(aSt[i].z); p[3] = f2tf(aSt[i].w);
        }
#pragma unroll
        for (int i = 0; i < BV; i++) {
            int n = tid % BN; int kb = tid / BN + i * (NTHR / BN);
            uint32_t* p = &Bs[st][n][4 * kb];
#pragma unroll
            for (int j = 0; j < 4; j++) p[j] = f2tf(bSt[i][j]);
        }
    };

    float acc[MT][NT2][4];
#pragma unroll
    for (int mt = 0; mt < MT; mt++)
#pragma unroll
        for (int nt = 0; nt < NT2; nt++)
#pragma unroll
            for (int j = 0; j < 4; j++) acc[mt][nt][j] = 0.f;

    auto comp = [&](int st) {
#pragma unroll
        for (int kt = 0; kt < 2; kt++) {
            uint32_t af[MT][4], bf[NT2][2];
#pragma unroll
            for (int mt = 0; mt < MT; mt++) {
                int r0 = wm * WTM + mt * 16 + g;
                af[mt][0] = As[st][r0    ][kt * 8 + tig];
                af[mt][1] = As[st][r0 + 8][kt * 8 + tig];
                af[mt][2] = As[st][r0    ][kt * 8 + tig + 4];
                af[mt][3] = As[st][r0 + 8][kt * 8 + tig + 4];
            }
#pragma unroll
            for (int nt = 0; nt < NT2; nt++) {
                int c0 = wn * WTN + nt * 8 + g;
                bf[nt][0] = Bs[st][c0][kt * 8 + tig];
                bf[nt][1] = Bs[st][c0][kt * 8 + tig + 4];
            }
#pragma unroll
            for (int mt = 0; mt < MT; mt++)
#pragma unroll
                for (int nt = 0; nt < NT2; nt++)
                    mma8(acc[mt][nt], af[mt], bf[nt]);
        }
    };

    loadG(0); storeS(0); __syncthreads();
    int cur = 0;
    for (int it = 1; it <= NK; it++) {
        if (it < NK) loadG(it * 16);
        comp(cur);
        if (it < NK) storeS(cur ^ 1);
        __syncthreads();
        cur ^= 1;
    }

#pragma unroll
    for (int mt = 0; mt < MT; mt++) {
        int r0 = m0 + wm * WTM + mt * 16 + g;
#pragma unroll
        for (int nt = 0; nt < NT2; nt++) {
            int col = n0 + wn * WTN + nt * 8 + 2 * tig;
            float v0 = acc[mt][nt][0], v1 = acc[mt][nt][1];
            float v2 = acc[mt][nt][2], v3 = acc[mt][nt][3];
            if (P.bias) {
                float b0f = P.bias[col], b1f = P.bias[col + 1];
                v0 += b0f; v1 += b1f; v2 += b0f; v3 += b1f;
            }
            *reinterpret_cast<float2*>(&C[(long long)r0 * ldc + col]) =
                make_float2(v0, v1);
            *reinterpret_cast<float2*>(&C[(long long)(r0 + 8) * ldc + col]) =
                make_float2(v2, v3);
        }
    }
}

// ---------------------------------------------------------------------------
// Generic NN tf32 GEMM with bias+resid epilogue (for post projection).
// ---------------------------------------------------------------------------
template <int BM, int BN, int WMS, int WNS>
__global__ void __launch_bounds__(WMS * WNS * 32)
tgemm(const float* __restrict__ A, const float* __restrict__ Bm,
      float* __restrict__ C, int K, int lda, int ldb, int ldc,
      const float* __restrict__ colBias,
      const float* __restrict__ resid, int ldr)
{
    constexpr int NTHR = WMS * WNS * 32;
    constexpr int BKP  = 20;
    constexpr int WTM  = BM / WMS, WTN = BN / WNS;
    constexpr int MT   = WTM / 16, NT2 = WTN / 8;
    constexpr int AV   = 4 * BM / NTHR;
    constexpr int BV   = 4 * BN / NTHR;

    __shared__ uint32_t As[2][BM][BKP];
    __shared__ uint32_t Bs[2][BN][BKP];

    const int m0 = blockIdx.y * BM, n0 = blockIdx.x * BN;
    const int tid = threadIdx.x, lane = tid & 31, wid = tid >> 5;
    const int g = lane >> 2, tig = lane & 3;
    const int wm = wid / WNS, wn = wid % WNS;

    float4 aSt[AV];
    float  bSt[BV][4];
    const int NK = K / 16;

    auto loadG = [&](int k0) {
#pragma unroll
        for (int i = 0; i < AV; i++) {
            int v = tid + i * NTHR; int row = v >> 2, c4 = v & 3;
            aSt[i] = *reinterpret_cast<const float4*>(
                A + (long long)(m0 + row) * lda + k0 + 4 * c4);
        }
#pragma unroll
        for (int i = 0; i < BV; i++) {
            int n = tid % BN; int kb = tid / BN + i * (NTHR / BN);
#pragma unroll
            for (int j = 0; j < 4; j++)
                bSt[i][j] = Bm[(long long)(k0 + kb * 4 + j) * ldb + n0 + n];
        }
    };

    auto storeS = [&](int st) {
#pragma unroll
        for (int i = 0; i < AV; i++) {
            int v = tid + i * NTHR; int row = v >> 2, c4 = v & 3;
            uint32_t* p = &As[st][row][4 * c4];
            p[0] = f2tf(aSt[i].x); p[1] = f2tf(aSt[i].y);
            p[2] = f2tf(aSt[i].z); p[3] = f2tf(aSt[i].w);
        }
#pragma unroll
        for (int i = 0; i < BV; i++) {
            int n = tid % BN; int kb = tid / BN + i * (NTHR / BN);
            uint32_t* p = &Bs[st][n][4 * kb];
#pragma unroll
            for (int j = 0; j < 4; j++) p[j] = f2tf(bSt[i][j]);
        }
    };

    float acc[MT][NT2][4];
#pragma unroll
    for (int mt = 0; mt < MT; mt++)
#pragma unroll
        for (int nt = 0; nt < NT2; nt++)
#pragma unroll
            for (int j = 0; j < 4; j++) acc[mt][nt][j] = 0.f;

    auto comp = [&](int st) {
#pragma unroll
        for (int kt = 0; kt < 2; kt++) {
            uint32_t af[MT][4], bf[NT2][2];
#pragma unroll
            for (int mt = 0; mt < MT; mt++) {
                int r0 = wm * WTM + mt * 16 + g;
                af[mt][0] = As[st][r0    ][kt * 8 + tig];
                af[mt][1] = As[st][r0 + 8][kt * 8 + tig];
                af[mt][2] = As[st][r0    ][kt * 8 + tig + 4];
                af[mt][3] = As[st][r0 + 8][kt * 8 + tig + 4];
            }
#pragma unroll
            for (int nt = 0; nt < NT2; nt++) {
                int c0 = wn * WTN + nt * 8 + g;
                bf[nt][0] = Bs[st][c0][kt * 8 + tig];
                bf[nt][1] = Bs[st][c0][kt * 8 + tig + 4];
            }
#pragma unroll
            for (int mt = 0; mt < MT; mt++)
#pragma unroll
                for (int nt = 0; nt < NT2; nt++)
                    mma8(acc[mt][nt], af[mt], bf[nt]);
        }
    };

    loadG(0); storeS(0); __syncthreads();
    int cur = 0;
    for (int it = 1; it <= NK; it++) {
        if (it < NK) loadG(it * 16);
        comp(cur);
        if (it < NK) storeS(cur ^ 1);
        __syncthreads();
        cur ^= 1;
    }

#pragma unroll
    for (int mt = 0; mt < MT; mt++) {
        int r0 = m0 + wm * WTM + mt * 16 + g;
#pragma unroll
        for (int nt = 0; nt < NT2; nt++) {
            int col = n0 + wn * WTN + nt * 8 + 2 * tig;
            float v0 = acc[mt][nt][0], v1 = acc[mt][nt][1];
            float v2 = acc[mt][nt][2], v3 = acc[mt][nt][3];
            if (colBias) {
                float b0f = colBias[col], b1f = colBias[col + 1];
                v0 += b0f; v1 += b1f; v2 += b0f; v3 += b1f;
            }
            if (resid) {
                v0 += resid[(long long)r0 * ldr + col];
                v1 += resid[(long long)r0 * ldr + col + 1];
                v2 += resid[(long long)(r0 + 8) * ldr + col];
                v3 += resid[(long long)(r0 + 8) * ldr + col + 1];
            }
            *reinterpret_cast<float2*>(&C[(long long)r0 * ldc + col]) =
                make_float2(v0, v1);
            *reinterpret_cast<float2*>(&C[(long long)(r0 + 8) * ldc + col]) =
                make_float2(v2, v3);
        }
    }
}

// ---------------------------------------------------------------------------
// Fused KS / cvec kernel (unchanged).
// ---------------------------------------------------------------------------
__global__ void ks_cvec_kernel(const float* __restrict__ rwb,
                               const float* __restrict__ rrb)
{
    const int gw = (blockIdx.x * blockDim.x + threadIdx.x) >> 5;
    const int lane = threadIdx.x & 31;
    if (gw >= B_ * N_ * S_) return;
    const int s = gw % S_;
    const int n = (gw / S_) % N_;
    const int b = gw / (S_ * N_);

    const long long khOff = (long long)(b * S_ + s) * D_ + n * H_;
    const long long rOff  = (long long)s * D_ + n * H_;

    float acc = 0.f;
#pragma unroll
    for (int h = lane; h < H_; h += 32) {
        float kv = g_kh[khOff + h];
        float rv = g_r[rOff + h];
        g_kh[khOff + h] = kv + rv;
        acc += rwb[n * H_ + h] * kv + rrb[n * H_ + h] * rv;
    }
#pragma unroll
    for (int o = 16; o; o >>= 1) acc += __shfl_xor_sync(~0u, acc, o);
    if (lane == 0) g_cvec[(long long)(b * N_ + n) * S_ + s] = acc;
}

// ---------------------------------------------------------------------------
// Fused flash attention (unchanged from round 6).
// ---------------------------------------------------------------------------
constexpr int FBQ = 64;
constexpr int FBK = 128;
constexpr int FQS = 68;
constexpr int FKS = 68;
constexpr int FVS = 68;
constexpr int FPS = 132;
constexpr int FKP_WORDS = FBK * FKS;
constexpr int FSMEM_WORDS = FBQ * FQS + FKP_WORDS + FBK * FVS + FBK;
constexpr int FSMEM_BYTES = FSMEM_WORDS * 4;

__global__ void __launch_bounds__(128) flash_kernel(const int* __restrict__ mask)
{
    extern __shared__ float sm[];
    float* Qs   = sm;
    float* KP   = Qs + FBQ * FQS;
    float* Vs   = KP + FKP_WORDS;
    float* sAdd = Vs + FBK * FVS;

    const int z = blockIdx.y;
    const int b = z >> 4, n = z & 15;
    const int q0 = blockIdx.x * FBQ;
    const int tid = threadIdx.x, lane = tid & 31, w = tid >> 5;
    const int g = lane >> 2, tig = lane & 3;
    const int r0 = w * 16 + g;

    const float* Qg = g_qh + (long long)b * S_ * D_ + n * H_;
    const float* Kg = g_kh + (long long)b * S_ * D_ + n * H_;
    const float* Vg = g_vh + (long long)b * S_ * D_ + n * H_;
    const float* cv = g_cvec + (long long)z * S_;
    const int*   mk = mask + b * S_;

#pragma unroll
    for (int i = 0; i < 8; i++) {
        int v = tid + i * 128;
        int row = v >> 4, c4 = v & 15;
        float4 t = *reinterpret_cast<const float4*>(
            Qg + (long long)(q0 + row) * D_ + 4 * c4);
        float* p = Qs + row * FQS + 4 * c4;
        p[0] = __uint_as_float(f2tf(t.x)); p[1] = __uint_as_float(f2tf(t.y));
        p[2] = __uint_as_float(f2tf(t.z)); p[3] = __uint_as_float(f2tf(t.w));
    }

    float Oa[8][4];
#pragma unroll
    for (int i = 0; i < 8; i++)
#pragma unroll
        for (int j = 0; j < 4; j++) Oa[i][j] = 0.f;
    float m0r = -3.0e38f, m1r = -3.0e38f, l0r = 0.f, l1r = 0.f;

    for (int kt = 0; kt < S_ / FBK; kt++) {
        __syncthreads();
        const int kb = kt * FBK;
#pragma unroll
        for (int i = 0; i < 16; i++) {
            int v = tid + i * 128;
            int row = v >> 4, c4 = v & 15;
            float4 t = *reinterpret_cast<const float4*>(
                Kg + (long long)(kb + row) * D_ + 4 * c4);
            float* p = KP + row * FKS + 4 * c4;
            p[0] = __uint_as_float(f2tf(t.x)); p[1] = __uint_as_float(f2tf(t.y));
            p[2] = __uint_as_float(f2tf(t.z)); p[3] = __uint_as_float(f2tf(t.w));
            float4 u = *reinterpret_cast<const float4*>(
                Vg + (long long)(kb + row) * D_ + 4 * c4);
            float* pv = Vs + row * FVS + 4 * c4;
            pv[0] = __uint_as_float(f2tf(u.x)); pv[1] = __uint_as_float(f2tf(u.y));
            pv[2] = __uint_as_float(f2tf(u.z)); pv[3] = __uint_as_float(f2tf(u.w));
        }
        sAdd[tid] = NORM_ * cv[kb + tid] - BIGC_ * (float)mk[kb + tid];
        __syncthreads();

        float Sa[16][4];
#pragma unroll
        for (int i = 0; i < 16; i++)
#pragma unroll
            for (int j = 0; j < 4; j++) Sa[i][j] = 0.f;
#pragma unroll
        for (int ks = 0; ks < 8; ks++) {
            uint32_t a[4];
            a[0] = __float_as_uint(Qs[ r0      * FQS + ks * 8 + tig]);
            a[1] = __float_as_uint(Qs[(r0 + 8) * FQS + ks * 8 + tig]);
            a[2] = __float_as_uint(Qs[ r0      * FQS + ks * 8 + tig + 4]);
            a[3] = __float_as_uint(Qs[(r0 + 8) * FQS + ks * 8 + tig + 4]);
#pragma unroll
            for (int nt = 0; nt < 16; nt++) {
                uint32_t bfr[2];
                bfr[0] = __float_as_uint(KP[(nt * 8 + g) * FKS + ks * 8 + tig]);
                bfr[1] = __float_as_uint(KP[(nt * 8 + g) * FKS + ks * 8 + tig + 4]);
                mma8(Sa[nt], a, bfr);
            }
        }
        __syncthreads();

        float tm0 = -3.0e38f, tm1 = -3.0e38f;
#pragma unroll
        for (int nt = 0; nt < 16; nt++) {
            int c = nt * 8 + 2 * tig;
            float a0 = sAdd[c], a1 = sAdd[c + 1];
            Sa[nt][0] = NORM_ * Sa[nt][0] + a0;
            Sa[nt][1] = NORM_ * Sa[nt][1] + a1;
            Sa[nt][2] = NORM_ * Sa[nt][2] + a0;
            Sa[nt][3] = NORM_ * Sa[nt][3] + a1;
            tm0 = fmaxf(tm0, fmaxf(Sa[nt][0], Sa[nt][1]));
            tm1 = fmaxf(tm1, fmaxf(Sa[nt][2], Sa[nt][3]));
        }
        tm0 = fmaxf(tm0, __shfl_xor_sync(~0u, tm0, 1));
        tm0 = fmaxf(tm0, __shfl_xor_sync(~0u, tm0, 2));
        tm1 = fmaxf(tm1, __shfl_xor_sync(~0u, tm1, 1));
        tm1 = fmaxf(tm1, __shfl_xor_sync(~0u, tm1, 2));
        float mn0 = fmaxf(m0r, tm0), mn1 = fmaxf(m1r, tm1);
        float sc0 = __expf(m0r - mn0), sc1 = __expf(m1r - mn1);
        m0r = mn0; m1r = mn1;

        float rs0 = 0.f, rs1 = 0.f;
#pragma unroll
        for (int nt = 0; nt < 16; nt++) {
            int c = nt * 8 + 2 * tig;
            float p0 = __expf(Sa[nt][0] - mn0);
            float p1 = __expf(Sa[nt][1] - mn0);
            float p2 = __expf(Sa[nt][2] - mn1);
            float p3 = __expf(Sa[nt][3] - mn1);
            rs0 += p0 + p1; rs1 += p2 + p3;
            KP[ r0      * FPS + c    ] = __uint_as_float(f2tf(p0));
            KP[ r0      * FPS + c + 1] = __uint_as_float(f2tf(p1));
            KP[(r0 + 8) * FPS + c    ] = __uint_as_float(f2tf(p2));
            KP[(r0 + 8) * FPS + c + 1] = __uint_as_float(f2tf(p3));
        }
        rs0 += __shfl_xor_sync(~0u, rs0, 1); rs0 += __shfl_xor_sync(~0u, rs0, 2);
        rs1 += __shfl_xor_sync(~0u, rs1, 1); rs1 += __shfl_xor_sync(~0u, rs1, 2);
        l0r = l0r * sc0 + rs0;
        l1r = l1r * sc1 + rs1;
#pragma unroll
        for (int nt = 0; nt < 8; nt++) {
            Oa[nt][0] *= sc0; Oa[nt][1] *= sc0;
            Oa[nt][2] *= sc1; Oa[nt][3] *= sc1;
        }
        __syncwarp();

#pragma unroll
        for (int ks = 0; ks < 16; ks++) {
            uint32_t a[4];
            a[0] = __float_as_uint(KP[ r0      * FPS + ks * 8 + tig]);
            a[1] = __float_as_uint(KP[(r0 + 8) * FPS + ks * 8 + tig]);
            a[2] = __float_as_uint(KP[ r0      * FPS + ks * 8 + tig + 4]);
            a[3] = __float_as_uint(KP[(r0 + 8) * FPS + ks * 8 + tig + 4]);
#pragma unroll
            for (int nt = 0; nt < 8; nt++) {
                uint32_t bfr[2];
                bfr[0] = __float_as_uint(Vs[(ks * 8 + tig    ) * FVS + nt * 8 + g]);
                bfr[1] = __float_as_uint(Vs[(ks * 8 + tig + 4) * FVS + nt * 8 + g]);
                mma8(Oa[nt], a, bfr);
            }
        }
    }

    const float inv0 = 1.0f / l0r, inv1 = 1.0f / l1r;
    float* Og = g_out + (long long)b * S_ * D_ + n * H_;
#pragma unroll
    for (int nt = 0; nt < 8; nt++) {
        int col = nt * 8 + 2 * tig;
        *reinterpret_cast<float2*>(
            Og + (long long)(q0 + r0) * D_ + col) =
            make_float2(Oa[nt][0] * inv0, Oa[nt][1] * inv0);
        *reinterpret_cast<float2*>(
            Og + (long long)(q0 + r0 + 8) * D_ + col) =
            make_float2(Oa[nt][2] * inv1, Oa[nt][3] * inv1);
    }
}

// ---------------------------------------------------------------------------
// LayerNorm in place on d_out rows. One block (256 thr) per row.
// ---------------------------------------------------------------------------
__global__ void __launch_bounds__(256)
ln_kernel(float* __restrict__ x, const float* __restrict__ gamma,
          const float* __restrict__ beta)
{
    float* p = x + (long long)blockIdx.x * D_;
    const int t = threadIdx.x;
    __shared__ float sred[8];

    float v[4];
    float s = 0.f;
#pragma unroll
    for (int i = 0; i < 4; i++) { v[i] = p[t + 256 * i]; s += v[i]; }
#pragma unroll
    for (int o = 16; o; o >>= 1) s += __shfl_xor_sync(~0u, s, o);
    if ((t & 31) == 0) sred[t >> 5] = s;
    __syncthreads();
    s = 0.f;
#pragma unroll
    for (int i = 0; i < 8; i++) s += sred[i];
    const float mean = s * (1.0f / D_);
    __syncthreads();

    float vs = 0.f;
#pragma unroll
    for (int i = 0; i < 4; i++) { float d = v[i] - mean; vs += d * d; }
#pragma unroll
    for (int o = 16; o; o >>= 1) vs += __shfl_xor_sync(~0u, vs, o);
    if ((t & 31) == 0) sred[t >> 5] = vs;
    __syncthreads();
    vs = 0.f;
#pragma unroll
    for (int i = 0; i < 8; i++) vs += sred[i];
    const float rstd = rsqrtf(vs * (1.0f / D_) + LNEPS_);

#pragma unroll
    for (int i = 0; i < 4; i++) {
        const int col = t + 256 * i;
        p[col] = (v[i] - mean) * rstd * gamma[col] + beta[col];
    }
}

// ---------------------------------------------------------------------------
// Host launcher
// ---------------------------------------------------------------------------
extern "C" void kernel_launch(void* const* d_in, const int* in_sizes, int n_in,
                              void* d_out, int out_size)
{
    const float* q        = (const float*)d_in[0];
    const float* k        = (const float*)d_in[1];
    const float* v        = (const float*)d_in[2];
    const float* pos_enc  = (const float*)d_in[3];
    const int*   mask     = (const int*)  d_in[4];
    const float* q_w      = (const float*)d_in[5];
    const float* k_w      = (const float*)d_in[6];
    const float* k_b      = (const float*)d_in[7];
    const float* v_w      = (const float*)d_in[8];
    const float* v_b      = (const float*)d_in[9];
    const float* rwb      = (const float*)d_in[10];
    const float* rrb      = (const float*)d_in[11];
    const float* r_kernel = (const float*)d_in[12];
    const float* post_w   = (const float*)d_in[13];
    const float* post_b   = (const float*)d_in[14];
    const float* ln_g     = (const float*)d_in[15];
    const float* ln_b     = (const float*)d_in[16];
    float* out = (float*)d_out;

    void* p;
    cudaGetSymbolAddress(&p, g_qh);     float* qh = (float*)p;
    cudaGetSymbolAddress(&p, g_kh);     float* kh = (float*)p;
    cudaGetSymbolAddress(&p, g_vh);     float* vh = (float*)p;
    cudaGetSymbolAddress(&p, g_r);      float* rr = (float*)p;
    cudaGetSymbolAddress(&p, g_rw);     float* rw = (float*)p;
    cudaGetSymbolAddress(&p, g_out);    float* ao = (float*)p;

    // 0. r_kernel transpose [N,D,H] -> [D, N*H]
    rk_transpose<<<64, 256>>>(r_kernel);

    // 1. Merged projections: z = {q, k, v, r(pos_enc)} in one launch
    {
        GemmBatch4 bs;
        bs.b[0] = { q,       q_w, nullptr, qh, B_ * S_ };
        bs.b[1] = { k,       k_w, k_b,     kh, B_ * S_ };
        bs.b[2] = { v,       v_w, v_b,     vh, B_ * S_ };
        bs.b[3] = { pos_enc, rw,  nullptr, rr, S_      };
        dim3 grid(D_ / 64, (B_ * S_) / 128, 4);
        tgemm_multi<128, 64, 4, 2><<<grid, 256>>>(bs, D_, D_, D_, D_);
    }

    // 2. KS = kh + r; cvec
    ks_cvec_kernel<<<(B_ * N_ * S_) / 8, 256>>>(rwb, rrb);

    // 3. Fused flash attention (scores + softmax + P@V) -> g_out
    {
        cudaFuncSetAttribute(flash_kernel,
                             cudaFuncAttributeMaxDynamicSharedMemorySize,
                             FSMEM_BYTES);
        dim3 grid(S_ / FBQ, B_ * N_);
        flash_kernel<<<grid, 128, FSMEM_BYTES>>>(mask);
    }

    // 4. post GEMM + bias + residual -> d_out
    {
        dim3 grid(D_ / 64, (B_ * S_) / 128, 1);
        tgemm<128, 64, 4, 2><<<grid, 256>>>(
            ao, post_w, out, D_, D_, D_, D_, post_b, q, D_);
    }

    // 5. LayerNorm in place
    ln_kernel<<<B_ * S_, 256>>>(out, ln_g, ln_b);
}

// round 9
// speedup vs baseline: 8.0728x; 1.0447x over previous
#include <cuda_runtime.h>
#include <math.h>
#include <stdint.h>

// Problem constants
constexpr int B_ = 2, S_ = 1024, D_ = 1024, N_ = 16, H_ = 64;
constexpr float NORM_ = 0.125f;       // 1/sqrt(64)
constexpr float BIGC_ = 1000000.0f;
constexpr float LNEPS_ = 1e-5f;

// Scratch (static device globals — no runtime allocation)
__device__ __align__(16) float g_qh[B_ * S_ * D_];
__device__ __align__(16) float g_kh[B_ * S_ * D_];          // becomes KS = kh + r
__device__ __align__(16) float g_vh[B_ * S_ * D_];
__device__ __align__(16) float g_r [S_ * D_];
__device__ __align__(16) float g_rw[D_ * D_];               // r_kernel transposed [D, N*H]
__device__ __align__(16) float g_cvec[B_ * N_ * S_];
__device__ __align__(16) float g_out[B_ * S_ * D_];

// ---------------------------------------------------------------------------
// tf32 helpers
// ---------------------------------------------------------------------------
__device__ __forceinline__ uint32_t f2tf(float x) {
    uint32_t r;
    asm("cvt.rna.tf32.f32 %0, %1;" : "=r"(r) : "f"(x));
    return r;
}

__device__ __forceinline__ void mma8(float* c, const uint32_t* a, const uint32_t* b) {
    asm volatile(
        "mma.sync.aligned.m16n8k8.row.col.f32.tf32.tf32.f32 "
        "{%0,%1,%2,%3},{%4,%5,%6,%7},{%8,%9},{%0,%1,%2,%3};\n"
        : "+f"(c[0]), "+f"(c[1]), "+f"(c[2]), "+f"(c[3])
        : "r"(a[0]), "r"(a[1]), "r"(a[2]), "r"(a[3]), "r"(b[0]), "r"(b[1]));
}

// ---------------------------------------------------------------------------
// r_kernel transpose: [N, D, H] -> g_rw [D, N*H].
// ---------------------------------------------------------------------------
__global__ void rk_transpose(const float* __restrict__ rk)
{
    const int idx = blockIdx.x * blockDim.x + threadIdx.x;   // 0 .. 16383
    const int d = idx >> 4, n = idx & 15;
    const float4* src = reinterpret_cast<const float4*>(
        rk + ((long long)n * D_ + d) * H_);
    float4* dst = reinterpret_cast<float4*>(g_rw + (long long)d * D_ + n * H_);
#pragma unroll
    for (int i = 0; i < 16; i++) dst[i] = src[i];
}

// ---------------------------------------------------------------------------
// Multi-batch NN tf32 GEMM (one launch for q/k/v/r projections).
// ---------------------------------------------------------------------------
struct GemmBatch {
    const float* A;
    const float* Bm;
    const float* bias;
    float*       C;
    int          M;
};
struct GemmBatch4 { GemmBatch b[4]; };

template <int BM, int BN, int WMS, int WNS>
__global__ void __launch_bounds__(WMS * WNS * 32)
tgemm_multi(GemmBatch4 bs, int K, int lda, int ldb, int ldc)
{
    constexpr int NTHR = WMS * WNS * 32;
    constexpr int BKP  = 20;
    constexpr int WTM  = BM / WMS, WTN = BN / WNS;
    constexpr int MT   = WTM / 16, NT2 = WTN / 8;
    constexpr int AV   = 4 * BM / NTHR;
    constexpr int BV   = 4 * BN / NTHR;

    const GemmBatch P = bs.b[blockIdx.z];
    const int m0 = blockIdx.y * BM, n0 = blockIdx.x * BN;
    if (m0 >= P.M) return;

    __shared__ uint32_t As[2][BM][BKP];
    __shared__ uint32_t Bs[2][BN][BKP];

    const float* A  = P.A;
    const float* Bm = P.Bm;
    float* C = P.C;

    const int tid = threadIdx.x, lane = tid & 31, wid = tid >> 5;
    const int g = lane >> 2, tig = lane & 3;
    const int wm = wid / WNS, wn = wid % WNS;

    float4 aSt[AV];
    float  bSt[BV][4];
    const int NK = K / 16;

    auto loadG = [&](int k0) {
#pragma unroll
        for (int i = 0; i < AV; i++) {
            int v = tid + i * NTHR; int row = v >> 2, c4 = v & 3;
            aSt[i] = *reinterpret_cast<const float4*>(
                A + (long long)(m0 + row) * lda + k0 + 4 * c4);
        }
#pragma unroll
        for (int i = 0; i < BV; i++) {
            int n = tid % BN; int kb = tid / BN + i * (NTHR / BN);
#pragma unroll
            for (int j = 0; j < 4; j++)
                bSt[i][j] = Bm[(long long)(k0 + kb * 4 + j) * ldb + n0 + n];
        }
    };

    auto storeS = [&](int st) {
#pragma unroll
        for (int i = 0; i < AV; i++) {
            int v = tid + i * NTHR; int row = v >> 2, c4 = v & 3;
            uint32_t* p = &As[st][row][4 * c4];
            p[0] = f2tf(aSt[i].x); p[1] = f2tf(aSt[i].y);
            p[2] = f2tf(aSt[i].z); p[3] = f2tf(aSt[i].w);
        }
#pragma unroll
        for (int i = 0; i < BV; i++) {
            int n = tid % BN; int kb = tid / BN + i * (NTHR / BN);
            uint32_t* p = &Bs[st][n][4 * kb];
#pragma unroll
            for (int j = 0; j < 4; j++) p[j] = f2tf(bSt[i][j]);
        }
    };

    float acc[MT][NT2][4];
#pragma unroll
    for (int mt = 0; mt < MT; mt++)
#pragma unroll
        for (int nt = 0; nt < NT2; nt++)
#pragma unroll
            for (int j = 0; j < 4; j++) acc[mt][nt][j] = 0.f;

    auto comp = [&](int st) {
#pragma unroll
        for (int kt = 0; kt < 2; kt++) {
            uint32_t af[MT][4], bf[NT2][2];
#pragma unroll
            for (int mt = 0; mt < MT; mt++) {
                int r0 = wm * WTM + mt * 16 + g;
                af[mt][0] = As[st][r0    ][kt * 8 + tig];
                af[mt][1] = As[st][r0 + 8][kt * 8 + tig];
                af[mt][2] = As[st][r0    ][kt * 8 + tig + 4];
                af[mt][3] = As[st][r0 + 8][kt * 8 + tig + 4];
            }
#pragma unroll
            for (int nt = 0; nt < NT2; nt++) {
                int c0 = wn * WTN + nt * 8 + g;
                bf[nt][0] = Bs[st][c0][kt * 8 + tig];
                bf[nt][1] = Bs[st][c0][kt * 8 + tig + 4];
            }
#pragma unroll
            for (int mt = 0; mt < MT; mt++)
#pragma unroll
                for (int nt = 0; nt < NT2; nt++)
                    mma8(acc[mt][nt], af[mt], bf[nt]);
        }
    };

    loadG(0); storeS(0); __syncthreads();
    int cur = 0;
    for (int it = 1; it <= NK; it++) {
        if (it < NK) loadG(it * 16);
        comp(cur);
        if (it < NK) storeS(cur ^ 1);
        __syncthreads();
        cur ^= 1;
    }

#pragma unroll
    for (int mt = 0; mt < MT; mt++) {
        int r0 = m0 + wm * WTM + mt * 16 + g;
#pragma unroll
        for (int nt = 0; nt < NT2; nt++) {
            int col = n0 + wn * WTN + nt * 8 + 2 * tig;
            float v0 = acc[mt][nt][0], v1 = acc[mt][nt][1];
            float v2 = acc[mt][nt][2], v3 = acc[mt][nt][3];
            if (P.bias) {
                float b0f = P.bias[col], b1f = P.bias[col + 1];
                v0 += b0f; v1 += b1f; v2 += b0f; v3 += b1f;
            }
            *reinterpret_cast<float2*>(&C[(long long)r0 * ldc + col]) =
                make_float2(v0, v1);
            *reinterpret_cast<float2*>(&C[(long long)(r0 + 8) * ldc + col]) =
                make_float2(v2, v3);
        }
    }
}

// ---------------------------------------------------------------------------
// Generic NN tf32 GEMM with bias+resid epilogue (for post projection).
// ---------------------------------------------------------------------------
template <int BM, int BN, int WMS, int WNS>
__global__ void __launch_bounds__(WMS * WNS * 32)
tgemm(const float* __restrict__ A, const float* __restrict__ Bm,
      float* __restrict__ C, int K, int lda, int ldb, int ldc,
      const float* __restrict__ colBias,
      const float* __restrict__ resid, int ldr)
{
    constexpr int NTHR = WMS * WNS * 32;
    constexpr int BKP  = 20;
    constexpr int WTM  = BM / WMS, WTN = BN / WNS;
    constexpr int MT   = WTM / 16, NT2 = WTN / 8;
    constexpr int AV   = 4 * BM / NTHR;
    constexpr int BV   = 4 * BN / NTHR;

    __shared__ uint32_t As[2][BM][BKP];
    __shared__ uint32_t Bs[2][BN][BKP];

    const int m0 = blockIdx.y * BM, n0 = blockIdx.x * BN;
    const int tid = threadIdx.x, lane = tid & 31, wid = tid >> 5;
    const int g = lane >> 2, tig = lane & 3;
    const int wm = wid / WNS, wn = wid % WNS;

    float4 aSt[AV];
    float  bSt[BV][4];
    const int NK = K / 16;

    auto loadG = [&](int k0) {
#pragma unroll
        for (int i = 0; i < AV; i++) {
            int v = tid + i * NTHR; int row = v >> 2, c4 = v & 3;
            aSt[i] = *reinterpret_cast<const float4*>(
                A + (long long)(m0 + row) * lda + k0 + 4 * c4);
        }
#pragma unroll
        for (int i = 0; i < BV; i++) {
            int n = tid % BN; int kb = tid / BN + i * (NTHR / BN);
#pragma unroll
            for (int j = 0; j < 4; j++)
                bSt[i][j] = Bm[(long long)(k0 + kb * 4 + j) * ldb + n0 + n];
        }
    };

    auto storeS = [&](int st) {
#pragma unroll
        for (int i = 0; i < AV; i++) {
            int v = tid + i * NTHR; int row = v >> 2, c4 = v & 3;
            uint32_t* p = &As[st][row][4 * c4];
            p[0] = f2tf(aSt[i].x); p[1] = f2tf(aSt[i].y);
            p[2] = f2tf(aSt[i].z); p[3] = f2tf(aSt[i].w);
        }
#pragma unroll
        for (int i = 0; i < BV; i++) {
            int n = tid % BN; int kb = tid / BN + i * (NTHR / BN);
            uint32_t* p = &Bs[st][n][4 * kb];
#pragma unroll
            for (int j = 0; j < 4; j++) p[j] = f2tf(bSt[i][j]);
        }
    };

    float acc[MT][NT2][4];
#pragma unroll
    for (int mt = 0; mt < MT; mt++)
#pragma unroll
        for (int nt = 0; nt < NT2; nt++)
#pragma unroll
            for (int j = 0; j < 4; j++) acc[mt][nt][j] = 0.f;

    auto comp = [&](int st) {
#pragma unroll
        for (int kt = 0; kt < 2; kt++) {
            uint32_t af[MT][4], bf[NT2][2];
#pragma unroll
            for (int mt = 0; mt < MT; mt++) {
                int r0 = wm * WTM + mt * 16 + g;
                af[mt][0] = As[st][r0    ][kt * 8 + tig];
                af[mt][1] = As[st][r0 + 8][kt * 8 + tig];
                af[mt][2] = As[st][r0    ][kt * 8 + tig + 4];
                af[mt][3] = As[st][r0 + 8][kt * 8 + tig + 4];
            }
#pragma unroll
            for (int nt = 0; nt < NT2; nt++) {
                int c0 = wn * WTN + nt * 8 + g;
                bf[nt][0] = Bs[st][c0][kt * 8 + tig];
                bf[nt][1] = Bs[st][c0][kt * 8 + tig + 4];
            }
#pragma unroll
            for (int mt = 0; mt < MT; mt++)
#pragma unroll
                for (int nt = 0; nt < NT2; nt++)
                    mma8(acc[mt][nt], af[mt], bf[nt]);
        }
    };

    loadG(0); storeS(0); __syncthreads();
    int cur = 0;
    for (int it = 1; it <= NK; it++) {
        if (it < NK) loadG(it * 16);
        comp(cur);
        if (it < NK) storeS(cur ^ 1);
        __syncthreads();
        cur ^= 1;
    }

#pragma unroll
    for (int mt = 0; mt < MT; mt++) {
        int r0 = m0 + wm * WTM + mt * 16 + g;
#pragma unroll
        for (int nt = 0; nt < NT2; nt++) {
            int col = n0 + wn * WTN + nt * 8 + 2 * tig;
            float v0 = acc[mt][nt][0], v1 = acc[mt][nt][1];
            float v2 = acc[mt][nt][2], v3 = acc[mt][nt][3];
            if (colBias) {
                float b0f = colBias[col], b1f = colBias[col + 1];
                v0 += b0f; v1 += b1f; v2 += b0f; v3 += b1f;
            }
            if (resid) {
                v0 += resid[(long long)r0 * ldr + col];
                v1 += resid[(long long)r0 * ldr + col + 1];
                v2 += resid[(long long)(r0 + 8) * ldr + col];
                v3 += resid[(long long)(r0 + 8) * ldr + col + 1];
            }
            *reinterpret_cast<float2*>(&C[(long long)r0 * ldc + col]) =
                make_float2(v0, v1);
            *reinterpret_cast<float2*>(&C[(long long)(r0 + 8) * ldc + col]) =
                make_float2(v2, v3);
        }
    }
}

// ---------------------------------------------------------------------------
// Fused KS / cvec kernel (unchanged).
// ---------------------------------------------------------------------------
__global__ void ks_cvec_kernel(const float* __restrict__ rwb,
                               const float* __restrict__ rrb)
{
    const int gw = (blockIdx.x * blockDim.x + threadIdx.x) >> 5;
    const int lane = threadIdx.x & 31;
    if (gw >= B_ * N_ * S_) return;
    const int s = gw % S_;
    const int n = (gw / S_) % N_;
    const int b = gw / (S_ * N_);

    const long long khOff = (long long)(b * S_ + s) * D_ + n * H_;
    const long long rOff  = (long long)s * D_ + n * H_;

    float acc = 0.f;
#pragma unroll
    for (int h = lane; h < H_; h += 32) {
        float kv = g_kh[khOff + h];
        float rv = g_r[rOff + h];
        g_kh[khOff + h] = kv + rv;
        acc += rwb[n * H_ + h] * kv + rrb[n * H_ + h] * rv;
    }
#pragma unroll
    for (int o = 16; o; o >>= 1) acc += __shfl_xor_sync(~0u, acc, o);
    if (lane == 0) g_cvec[(long long)(b * N_ + n) * S_ + s] = acc;
}

// ---------------------------------------------------------------------------
// Fused flash attention. FBQ=64 q-rows, FBK=64 keys per tile.
// smem ~52.3 KB -> 4 CTAs/SM (vs 2 with FBK=128).
// ---------------------------------------------------------------------------
constexpr int FBQ = 64;
constexpr int FBK = 64;
constexpr int FQS = 68;     // Q row stride
constexpr int FKS = 68;     // K / P row stride
constexpr int FVS = 72;     // V row stride (8*tig+g conflict-free frag loads)
constexpr int FSMEM_WORDS = FBQ * FQS + FBK * FKS + FBK * FVS + FBK;
constexpr int FSMEM_BYTES = FSMEM_WORDS * 4;   // 53,504 B? (4352+4352+4608+64)*4 = 53,504

__global__ void __launch_bounds__(128) flash_kernel(const int* __restrict__ mask)
{
    extern __shared__ float sm[];
    float* Qs   = sm;                     // [64][68]
    float* KP   = Qs + FBQ * FQS;         // K [64][68] then P [64][68]
    float* Vs   = KP + FBK * FKS;         // [64][72]
    float* sAdd = Vs + FBK * FVS;         // [64]

    const int z = blockIdx.y;
    const int b = z >> 4, n = z & 15;
    const int q0 = blockIdx.x * FBQ;
    const int tid = threadIdx.x, lane = tid & 31, w = tid >> 5;
    const int g = lane >> 2, tig = lane & 3;
    const int r0 = w * 16 + g;

    const float* Qg = g_qh + (long long)b * S_ * D_ + n * H_;
    const float* Kg = g_kh + (long long)b * S_ * D_ + n * H_;
    const float* Vg = g_vh + (long long)b * S_ * D_ + n * H_;
    const float* cv = g_cvec + (long long)z * S_;
    const int*   mk = mask + b * S_;

    // Load Q tile (64 x 64) as tf32
#pragma unroll
    for (int i = 0; i < 8; i++) {
        int v = tid + i * 128;
        int row = v >> 4, c4 = v & 15;
        float4 t = *reinterpret_cast<const float4*>(
            Qg + (long long)(q0 + row) * D_ + 4 * c4);
        float* p = Qs + row * FQS + 4 * c4;
        p[0] = __uint_as_float(f2tf(t.x)); p[1] = __uint_as_float(f2tf(t.y));
        p[2] = __uint_as_float(f2tf(t.z)); p[3] = __uint_as_float(f2tf(t.w));
    }

    float Oa[8][4];
#pragma unroll
    for (int i = 0; i < 8; i++)
#pragma unroll
        for (int j = 0; j < 4; j++) Oa[i][j] = 0.f;
    float m0r = -3.0e38f, m1r = -3.0e38f, l0r = 0.f, l1r = 0.f;

    for (int kt = 0; kt < S_ / FBK; kt++) {
        __syncthreads();   // prior-tile P/V reads done; Q store done (iter 0)
        const int kb = kt * FBK;
#pragma unroll
        for (int i = 0; i < 8; i++) {
            int v = tid + i * 128;          // 64 rows * 16 float4
            int row = v >> 4, c4 = v & 15;
            float4 t = *reinterpret_cast<const float4*>(
                Kg + (long long)(kb + row) * D_ + 4 * c4);
            float* p = KP + row * FKS + 4 * c4;
            p[0] = __uint_as_float(f2tf(t.x)); p[1] = __uint_as_float(f2tf(t.y));
            p[2] = __uint_as_float(f2tf(t.z)); p[3] = __uint_as_float(f2tf(t.w));
            float4 u = *reinterpret_cast<const float4*>(
                Vg + (long long)(kb + row) * D_ + 4 * c4);
            float* pv = Vs + row * FVS + 4 * c4;
            pv[0] = __uint_as_float(f2tf(u.x)); pv[1] = __uint_as_float(f2tf(u.y));
            pv[2] = __uint_as_float(f2tf(u.z)); pv[3] = __uint_as_float(f2tf(u.w));
        }
        if (tid < FBK)
            sAdd[tid] = NORM_ * cv[kb + tid] - BIGC_ * (float)mk[kb + tid];
        __syncthreads();

        // S = Q @ K^T : per-warp 16 x 64
        float Sa[8][4];
#pragma unroll
        for (int i = 0; i < 8; i++)
#pragma unroll
            for (int j = 0; j < 4; j++) Sa[i][j] = 0.f;
#pragma unroll
        for (int ks = 0; ks < 8; ks++) {
            uint32_t a[4];
            a[0] = __float_as_uint(Qs[ r0      * FQS + ks * 8 + tig]);
            a[1] = __float_as_uint(Qs[(r0 + 8) * FQS + ks * 8 + tig]);
            a[2] = __float_as_uint(Qs[ r0      * FQS + ks * 8 + tig + 4]);
            a[3] = __float_as_uint(Qs[(r0 + 8) * FQS + ks * 8 + tig + 4]);
#pragma unroll
            for (int nt = 0; nt < 8; nt++) {
                uint32_t bfr[2];
                bfr[0] = __float_as_uint(KP[(nt * 8 + g) * FKS + ks * 8 + tig]);
                bfr[1] = __float_as_uint(KP[(nt * 8 + g) * FKS + ks * 8 + tig + 4]);
                mma8(Sa[nt], a, bfr);
            }
        }
        __syncthreads();   // all warps finished reading K from KP

        // Epilogue + online softmax
        float tm0 = -3.0e38f, tm1 = -3.0e38f;
#pragma unroll
        for (int nt = 0; nt < 8; nt++) {
            int c = nt * 8 + 2 * tig;
            float a0 = sAdd[c], a1 = sAdd[c + 1];
            Sa[nt][0] = NORM_ * Sa[nt][0] + a0;
            Sa[nt][1] = NORM_ * Sa[nt][1] + a1;
            Sa[nt][2] = NORM_ * Sa[nt][2] + a0;
            Sa[nt][3] = NORM_ * Sa[nt][3] + a1;
            tm0 = fmaxf(tm0, fmaxf(Sa[nt][0], Sa[nt][1]));
            tm1 = fmaxf(tm1, fmaxf(Sa[nt][2], Sa[nt][3]));
        }
        tm0 = fmaxf(tm0, __shfl_xor_sync(~0u, tm0, 1));
        tm0 = fmaxf(tm0, __shfl_xor_sync(~0u, tm0, 2));
        tm1 = fmaxf(tm1, __shfl_xor_sync(~0u, tm1, 1));
        tm1 = fmaxf(tm1, __shfl_xor_sync(~0u, tm1, 2));
        float mn0 = fmaxf(m0r, tm0), mn1 = fmaxf(m1r, tm1);
        float sc0 = __expf(m0r - mn0), sc1 = __expf(m1r - mn1);
        m0r = mn0; m1r = mn1;

        float rs0 = 0.f, rs1 = 0.f;
#pragma unroll
        for (int nt = 0; nt < 8; nt++) {
            int c = nt * 8 + 2 * tig;
            float p0 = __expf(Sa[nt][0] - mn0);
            float p1 = __expf(Sa[nt][1] - mn0);
            float p2 = __expf(Sa[nt][2] - mn1);
            float p3 = __expf(Sa[nt][3] - mn1);
            rs0 += p0 + p1; rs1 += p2 + p3;
            KP[ r0      * FKS + c    ] = __uint_as_float(f2tf(p0));
            KP[ r0      * FKS + c + 1] = __uint_as_float(f2tf(p1));
            KP[(r0 + 8) * FKS + c    ] = __uint_as_float(f2tf(p2));
            KP[(r0 + 8) * FKS + c + 1] = __uint_as_float(f2tf(p3));
        }
        rs0 += __shfl_xor_sync(~0u, rs0, 1); rs0 += __shfl_xor_sync(~0u, rs0, 2);
        rs1 += __shfl_xor_sync(~0u, rs1, 1); rs1 += __shfl_xor_sync(~0u, rs1, 2);
        l0r = l0r * sc0 + rs0;
        l1r = l1r * sc1 + rs1;
#pragma unroll
        for (int nt = 0; nt < 8; nt++) {
            Oa[nt][0] *= sc0; Oa[nt][1] *= sc0;
            Oa[nt][2] *= sc1; Oa[nt][3] *= sc1;
        }
        __syncwarp();      // P visible within warp (A-frags are own 16 rows)

        // O += P(16x64) @ V(64x64)
#pragma unroll
        for (int ks = 0; ks < 8; ks++) {
            uint32_t a[4];
            a[0] = __float_as_uint(KP[ r0      * FKS + ks * 8 + tig]);
            a[1] = __float_as_uint(KP[(r0 + 8) * FKS + ks * 8 + tig]);
            a[2] = __float_as_uint(KP[ r0      * FKS + ks * 8 + tig + 4]);
            a[3] = __float_as_uint(KP[(r0 + 8) * FKS + ks * 8 + tig + 4]);
#pragma unroll
            for (int nt = 0; nt < 8; nt++) {
                uint32_t bfr[2];
                bfr[0] = __float_as_uint(Vs[(ks * 8 + tig    ) * FVS + nt * 8 + g]);
                bfr[1] = __float_as_uint(Vs[(ks * 8 + tig + 4) * FVS + nt * 8 + g]);
                mma8(Oa[nt], a, bfr);
            }
        }
    }

    // Normalize and write out
    const float inv0 = 1.0f / l0r, inv1 = 1.0f / l1r;
    float* Og = g_out + (long long)b * S_ * D_ + n * H_;
#pragma unroll
    for (int nt = 0; nt < 8; nt++) {
        int col = nt * 8 + 2 * tig;
        *reinterpret_cast<float2*>(
            Og + (long long)(q0 + r0) * D_ + col) =
            make_float2(Oa[nt][0] * inv0, Oa[nt][1] * inv0);
        *reinterpret_cast<float2*>(
            Og + (long long)(q0 + r0 + 8) * D_ + col) =
            make_float2(Oa[nt][2] * inv1, Oa[nt][3] * inv1);
    }
}

// ---------------------------------------------------------------------------
// LayerNorm in place on d_out rows. One block (256 thr) per row.
// ---------------------------------------------------------------------------
__global__ void __launch_bounds__(256)
ln_kernel(float* __restrict__ x, const float* __restrict__ gamma,
          const float* __restrict__ beta)
{
    float* p = x + (long long)blockIdx.x * D_;
    const int t = threadIdx.x;
    __shared__ float sred[8];

    float v[4];
    float s = 0.f;
#pragma unroll
    for (int i = 0; i < 4; i++) { v[i] = p[t + 256 * i]; s += v[i]; }
#pragma unroll
    for (int o = 16; o; o >>= 1) s += __shfl_xor_sync(~0u, s, o);
    if ((t & 31) == 0) sred[t >> 5] = s;
    __syncthreads();
    s = 0.f;
#pragma unroll
    for (int i = 0; i < 8; i++) s += sred[i];
    const float mean = s * (1.0f / D_);
    __syncthreads();

    float vs = 0.f;
#pragma unroll
    for (int i = 0; i < 4; i++) { float d = v[i] - mean; vs += d * d; }
#pragma unroll
    for (int o = 16; o; o >>= 1) vs += __shfl_xor_sync(~0u, vs, o);
    if ((t & 31) == 0) sred[t >> 5] = vs;
    __syncthreads();
    vs = 0.f;
#pragma unroll
    for (int i = 0; i < 8; i++) vs += sred[i];
    const float rstd = rsqrtf(vs * (1.0f / D_) + LNEPS_);

#pragma unroll
    for (int i = 0; i < 4; i++) {
        const int col = t + 256 * i;
        p[col] = (v[i] - mean) * rstd * gamma[col] + beta[col];
    }
}

// ---------------------------------------------------------------------------
// Host launcher
// ---------------------------------------------------------------------------
extern "C" void kernel_launch(void* const* d_in, const int* in_sizes, int n_in,
                              void* d_out, int out_size)
{
    const float* q        = (const float*)d_in[0];
    const float* k        = (const float*)d_in[1];
    const float* v        = (const float*)d_in[2];
    const float* pos_enc  = (const float*)d_in[3];
    const int*   mask     = (const int*)  d_in[4];
    const float* q_w      = (const float*)d_in[5];
    const float* k_w      = (const float*)d_in[6];
    const float* k_b      = (const float*)d_in[7];
    const float* v_w      = (const float*)d_in[8];
    const float* v_b      = (const float*)d_in[9];
    const float* rwb      = (const float*)d_in[10];
    const float* rrb      = (const float*)d_in[11];
    const float* r_kernel = (const float*)d_in[12];
    const float* post_w   = (const float*)d_in[13];
    const float* post_b   = (const float*)d_in[14];
    const float* ln_g     = (const float*)d_in[15];
    const float* ln_b     = (const float*)d_in[16];
    float* out = (float*)d_out;

    void* p;
    cudaGetSymbolAddress(&p, g_qh);     float* qh = (float*)p;
    cudaGetSymbolAddress(&p, g_kh);     float* kh = (float*)p;
    cudaGetSymbolAddress(&p, g_vh);     float* vh = (float*)p;
    cudaGetSymbolAddress(&p, g_r);      float* rr = (float*)p;
    cudaGetSymbolAddress(&p, g_rw);     float* rw = (float*)p;
    cudaGetSymbolAddress(&p, g_out);    float* ao = (float*)p;

    // 0. r_kernel transpose [N,D,H] -> [D, N*H]
    rk_transpose<<<64, 256>>>(r_kernel);

    // 1. Merged projections: z = {q, k, v, r(pos_enc)} in one launch
    {
        GemmBatch4 bs;
        bs.b[0] = { q,       q_w, nullptr, qh, B_ * S_ };
        bs.b[1] = { k,       k_w, k_b,     kh, B_ * S_ };
        bs.b[2] = { v,       v_w, v_b,     vh, B_ * S_ };
        bs.b[3] = { pos_enc, rw,  nullptr, rr, S_      };
        dim3 grid(D_ / 64, (B_ * S_) / 128, 4);
        tgemm_multi<128, 64, 4, 2><<<grid, 256>>>(bs, D_, D_, D_, D_);
    }

    // 2. KS = kh + r; cvec
    ks_cvec_kernel<<<(B_ * N_ * S_) / 8, 256>>>(rwb, rrb);

    // 3. Fused flash attention (scores + softmax + P@V) -> g_out
    {
        cudaFuncSetAttribute(flash_kernel,
                             cudaFuncAttributeMaxDynamicSharedMemorySize,
                             FSMEM_BYTES);
        dim3 grid(S_ / FBQ, B_ * N_);
        flash_kernel<<<grid, 128, FSMEM_BYTES>>>(mask);
    }

    // 4. post GEMM + bias + residual -> d_out
    {
        dim3 grid(D_ / 64, (B_ * S_) / 128, 1);
        tgemm<128, 64, 4, 2><<<grid, 256>>>(
            ao, post_w, out, D_, D_, D_, D_, post_b, q, D_);
    }

    // 5. LayerNorm in place
    ln_kernel<<<B_ * S_, 256>>>(out, ln_g, ln_b);
}

// round 11
// speedup vs baseline: 8.5662x; 1.0611x over previous
#include <cuda_runtime.h>
#include <math.h>
#include <stdint.h>

// Problem constants
constexpr int B_ = 2, S_ = 1024, D_ = 1024, N_ = 16, H_ = 64;
constexpr float NORM_ = 0.125f;       // 1/sqrt(64)
constexpr float BIGC_ = 1000000.0f;
constexpr float LNEPS_ = 1e-5f;

// Scratch (static device globals — no runtime allocation)
__device__ __align__(16) float g_qh[B_ * S_ * D_];
__device__ __align__(16) float g_kh[B_ * S_ * D_];          // becomes KS = kh + r
__device__ __align__(16) float g_vh[B_ * S_ * D_];
__device__ __align__(16) float g_r [S_ * D_];
__device__ __align__(16) float g_rw[D_ * D_];               // r_kernel transposed [D, N*H]
__device__ __align__(16) float g_cvec[B_ * N_ * S_];
__device__ __align__(16) float g_out[B_ * S_ * D_];

// ---------------------------------------------------------------------------
// tf32 helpers
// ---------------------------------------------------------------------------
__device__ __forceinline__ uint32_t f2tf(float x) {
    uint32_t r;
    asm("cvt.rna.tf32.f32 %0, %1;" : "=r"(r) : "f"(x));
    return r;
}

__device__ __forceinline__ void mma8(float* c, const uint32_t* a, const uint32_t* b) {
    asm volatile(
        "mma.sync.aligned.m16n8k8.row.col.f32.tf32.tf32.f32 "
        "{%0,%1,%2,%3},{%4,%5,%6,%7},{%8,%9},{%0,%1,%2,%3};\n"
        : "+f"(c[0]), "+f"(c[1]), "+f"(c[2]), "+f"(c[3])
        : "r"(a[0]), "r"(a[1]), "r"(a[2]), "r"(a[3]), "r"(b[0]), "r"(b[1]));
}

// ---------------------------------------------------------------------------
// r_kernel transpose: [N, D, H] -> g_rw [D, N*H].
// ---------------------------------------------------------------------------
__global__ void rk_transpose(const float* __restrict__ rk)
{
    const int idx = blockIdx.x * blockDim.x + threadIdx.x;   // 0 .. 16383
    const int d = idx >> 4, n = idx & 15;
    const float4* src = reinterpret_cast<const float4*>(
        rk + ((long long)n * D_ + d) * H_);
    float4* dst = reinterpret_cast<float4*>(g_rw + (long long)d * D_ + n * H_);
#pragma unroll
    for (int i = 0; i < 16; i++) dst[i] = src[i];
}

// ---------------------------------------------------------------------------
// Multi-batch NN tf32 GEMM (one launch for q/k/v/r projections).
// ---------------------------------------------------------------------------
struct GemmBatch {
    const float* A;
    const float* Bm;
    const float* bias;
    float*       C;
    int          M;
};
struct GemmBatch4 { GemmBatch b[4]; };

template <int BM, int BN, int WMS, int WNS>
__global__ void __launch_bounds__(WMS * WNS * 32)
tgemm_multi(GemmBatch4 bs, int K, int lda, int ldb, int ldc)
{
    constexpr int NTHR = WMS * WNS * 32;
    constexpr int BKP  = 20;
    constexpr int WTM  = BM / WMS, WTN = BN / WNS;
    constexpr int MT   = WTM / 16, NT2 = WTN / 8;
    constexpr int AV   = 4 * BM / NTHR;
    constexpr int BV   = 4 * BN / NTHR;

    const GemmBatch P = bs.b[blockIdx.z];
    const int m0 = blockIdx.y * BM, n0 = blockIdx.x * BN;
    if (m0 >= P.M) return;

    __shared__ uint32_t As[2][BM][BKP];
    __shared__ uint32_t Bs[2][BN][BKP];

    const float* A  = P.A;
    const float* Bm = P.Bm;
    float* C = P.C;

    const int tid = threadIdx.x, lane = tid & 31, wid = tid >> 5;
    const int g = lane >> 2, tig = lane & 3;
    const int wm = wid / WNS, wn = wid % WNS;

    float4 aSt[AV];
    float  bSt[BV][4];
    const int NK = K / 16;

    auto loadG = [&](int k0) {
#pragma unroll
        for (int i = 0; i < AV; i++) {
            int v = tid + i * NTHR; int row = v >> 2, c4 = v & 3;
            aSt[i] = *reinterpret_cast<const float4*>(
                A + (long long)(m0 + row) * lda + k0 + 4 * c4);
        }
#pragma unroll
        for (int i = 0; i < BV; i++) {
            int n = tid % BN; int kb = tid / BN + i * (NTHR / BN);
#pragma unroll
            for (int j = 0; j < 4; j++)
                bSt[i][j] = Bm[(long long)(k0 + kb * 4 + j) * ldb + n0 + n];
        }
    };

    auto storeS = [&](int st) {
#pragma unroll
        for (int i = 0; i < AV; i++) {
            int v = tid + i * NTHR; int row = v >> 2, c4 = v & 3;
            uint32_t* p = &As[st][row][4 * c4];
            p[0] = f2tf(aSt[i].x); p[1] = f2tf(aSt[i].y);
            p[2] = f2tf(aSt[i].z); p[3] = f2tf(aSt[i].w);
        }
#pragma unroll
        for (int i = 0; i < BV; i++) {
            int n = tid % BN; int kb = tid / BN + i * (NTHR / BN);
            uint32_t* p = &Bs[st][n][4 * kb];
#pragma unroll
            for (int j = 0; j < 4; j++) p[j] = f2tf(bSt[i][j]);
        }
    };

    float acc[MT][NT2][4];
#pragma unroll
    for (int mt = 0; mt < MT; mt++)
#pragma unroll
        for (int nt = 0; nt < NT2; nt++)
#pragma unroll
            for (int j = 0; j < 4; j++) acc[mt][nt][j] = 0.f;

    auto comp = [&](int st) {
#pragma unroll
        for (int kt = 0; kt < 2; kt++) {
            uint32_t af[MT][4], bf[NT2][2];
#pragma unroll
            for (int mt = 0; mt < MT; mt++) {
                int r0 = wm * WTM + mt * 16 + g;
                af[mt][0] = As[st][r0    ][kt * 8 + tig];
                af[mt][1] = As[st][r0 + 8][kt * 8 + tig];
                af[mt][2] = As[st][r0    ][kt * 8 + tig + 4];
                af[mt][3] = As[st][r0 + 8][kt * 8 + tig + 4];
            }
#pragma unroll
            for (int nt = 0; nt < NT2; nt++) {
                int c0 = wn * WTN + nt * 8 + g;
                bf[nt][0] = Bs[st][c0][kt * 8 + tig];
                bf[nt][1] = Bs[st][c0][kt * 8 + tig + 4];
            }
#pragma unroll
            for (int mt = 0; mt < MT; mt++)
#pragma unroll
                for (int nt = 0; nt < NT2; nt++)
                    mma8(acc[mt][nt], af[mt], bf[nt]);
        }
    };

    loadG(0); storeS(0); __syncthreads();
    int cur = 0;
    for (int it = 1; it <= NK; it++) {
        if (it < NK) loadG(it * 16);
        comp(cur);
        if (it < NK) storeS(cur ^ 1);
        __syncthreads();
        cur ^= 1;
    }

#pragma unroll
    for (int mt = 0; mt < MT; mt++) {
        int r0 = m0 + wm * WTM + mt * 16 + g;
#pragma unroll
        for (int nt = 0; nt < NT2; nt++) {
            int col = n0 + wn * WTN + nt * 8 + 2 * tig;
            float v0 = acc[mt][nt][0], v1 = acc[mt][nt][1];
            float v2 = acc[mt][nt][2], v3 = acc[mt][nt][3];
            if (P.bias) {
                float b0f = P.bias[col], b1f = P.bias[col + 1];
                v0 += b0f; v1 += b1f; v2 += b0f; v3 += b1f;
            }
            *reinterpret_cast<float2*>(&C[(long long)r0 * ldc + col]) =
                make_float2(v0, v1);
            *reinterpret_cast<float2*>(&C[(long long)(r0 + 8) * ldc + col]) =
                make_float2(v2, v3);
        }
    }
}

// ---------------------------------------------------------------------------
// Generic NN tf32 GEMM with bias+resid epilogue (for post projection).
// ---------------------------------------------------------------------------
template <int BM, int BN, int WMS, int WNS>
__global__ void __launch_bounds__(WMS * WNS * 32)
tgemm(const float* __restrict__ A, const float* __restrict__ Bm,
      float* __restrict__ C, int K, int lda, int ldb, int ldc,
      const float* __restrict__ colBias,
      const float* __restrict__ resid, int ldr)
{
    constexpr int NTHR = WMS * WNS * 32;
    constexpr int BKP  = 20;
    constexpr int WTM  = BM / WMS, WTN = BN / WNS;
    constexpr int MT   = WTM / 16, NT2 = WTN / 8;
    constexpr int AV   = 4 * BM / NTHR;
    constexpr int BV   = 4 * BN / NTHR;

    __shared__ uint32_t As[2][BM][BKP];
    __shared__ uint32_t Bs[2][BN][BKP];

    const int m0 = blockIdx.y * BM, n0 = blockIdx.x * BN;
    const int tid = threadIdx.x, lane = tid & 31, wid = tid >> 5;
    const int g = lane >> 2, tig = lane & 3;
    const int wm = wid / WNS, wn = wid % WNS;

    float4 aSt[AV];
    float  bSt[BV][4];
    const int NK = K / 16;

    auto loadG = [&](int k0) {
#pragma unroll
        for (int i = 0; i < AV; i++) {
            int v = tid + i * NTHR; int row = v >> 2, c4 = v & 3;
            aSt[i] = *reinterpret_cast<const float4*>(
                A + (long long)(m0 + row) * lda + k0 + 4 * c4);
        }
#pragma unroll
        for (int i = 0; i < BV; i++) {
            int n = tid % BN; int kb = tid / BN + i * (NTHR / BN);
#pragma unroll
            for (int j = 0; j < 4; j++)
                bSt[i][j] = Bm[(long long)(k0 + kb * 4 + j) * ldb + n0 + n];
        }
    };

    auto storeS = [&](int st) {
#pragma unroll
        for (int i = 0; i < AV; i++) {
            int v = tid + i * NTHR; int row = v >> 2, c4 = v & 3;
            uint32_t* p = &As[st][row][4 * c4];
            p[0] = f2tf(aSt[i].x); p[1] = f2tf(aSt[i].y);
            p[2] = f2tf(aSt[i].z); p[3] = f2tf(aSt[i].w);
        }
#pragma unroll
        for (int i = 0; i < BV; i++) {
            int n = tid % BN; int kb = tid / BN + i * (NTHR / BN);
            uint32_t* p = &Bs[st][n][4 * kb];
#pragma unroll
            for (int j = 0; j < 4; j++) p[j] = f2tf(bSt[i][j]);
        }
    };

    float acc[MT][NT2][4];
#pragma unroll
    for (int mt = 0; mt < MT; mt++)
#pragma unroll
        for (int nt = 0; nt < NT2; nt++)
#pragma unroll
            for (int j = 0; j < 4; j++) acc[mt][nt][j] = 0.f;

    auto comp = [&](int st) {
#pragma unroll
        for (int kt = 0; kt < 2; kt++) {
            uint32_t af[MT][4], bf[NT2][2];
#pragma unroll
            for (int mt = 0; mt < MT; mt++) {
                int r0 = wm * WTM + mt * 16 + g;
                af[mt][0] = As[st][r0    ][kt * 8 + tig];
                af[mt][1] = As[st][r0 + 8][kt * 8 + tig];
                af[mt][2] = As[st][r0    ][kt * 8 + tig + 4];
                af[mt][3] = As[st][r0 + 8][kt * 8 + tig + 4];
            }
#pragma unroll
            for (int nt = 0; nt < NT2; nt++) {
                int c0 = wn * WTN + nt * 8 + g;
                bf[nt][0] = Bs[st][c0][kt * 8 + tig];
                bf[nt][1] = Bs[st][c0][kt * 8 + tig + 4];
            }
#pragma unroll
            for (int mt = 0; mt < MT; mt++)
#pragma unroll
                for (int nt = 0; nt < NT2; nt++)
                    mma8(acc[mt][nt], af[mt], bf[nt]);
        }
    };

    loadG(0); storeS(0); __syncthreads();
    int cur = 0;
    for (int it = 1; it <= NK; it++) {
        if (it < NK) loadG(it * 16);
        comp(cur);
        if (it < NK) storeS(cur ^ 1);
        __syncthreads();
        cur ^= 1;
    }

#pragma unroll
    for (int mt = 0; mt < MT; mt++) {
        int r0 = m0 + wm * WTM + mt * 16 + g;
#pragma unroll
        for (int nt = 0; nt < NT2; nt++) {
            int col = n0 + wn * WTN + nt * 8 + 2 * tig;
            float v0 = acc[mt][nt][0], v1 = acc[mt][nt][1];
            float v2 = acc[mt][nt][2], v3 = acc[mt][nt][3];
            if (colBias) {
                float b0f = colBias[col], b1f = colBias[col + 1];
                v0 += b0f; v1 += b1f; v2 += b0f; v3 += b1f;
            }
            if (resid) {
                v0 += resid[(long long)r0 * ldr + col];
                v1 += resid[(long long)r0 * ldr + col + 1];
                v2 += resid[(long long)(r0 + 8) * ldr + col];
                v3 += resid[(long long)(r0 + 8) * ldr + col + 1];
            }
            *reinterpret_cast<float2*>(&C[(long long)r0 * ldc + col]) =
                make_float2(v0, v1);
            *reinterpret_cast<float2*>(&C[(long long)(r0 + 8) * ldc + col]) =
                make_float2(v2, v3);
        }
    }
}

// ---------------------------------------------------------------------------
// Fused KS / cvec kernel (unchanged).
// ---------------------------------------------------------------------------
__global__ void ks_cvec_kernel(const float* __restrict__ rwb,
                               const float* __restrict__ rrb)
{
    const int gw = (blockIdx.x * blockDim.x + threadIdx.x) >> 5;
    const int lane = threadIdx.x & 31;
    if (gw >= B_ * N_ * S_) return;
    const int s = gw % S_;
    const int n = (gw / S_) % N_;
    const int b = gw / (S_ * N_);

    const long long khOff = (long long)(b * S_ + s) * D_ + n * H_;
    const long long rOff  = (long long)s * D_ + n * H_;

    float acc = 0.f;
#pragma unroll
    for (int h = lane; h < H_; h += 32) {
        float kv = g_kh[khOff + h];
        float rv = g_r[rOff + h];
        g_kh[khOff + h] = kv + rv;
        acc += rwb[n * H_ + h] * kv + rrb[n * H_ + h] * rv;
    }
#pragma unroll
    for (int o = 16; o; o >>= 1) acc += __shfl_xor_sync(~0u, acc, o);
    if (lane == 0) g_cvec[(long long)(b * N_ + n) * S_ + s] = acc;
}

// ---------------------------------------------------------------------------
// Fused flash attention. FBQ=128 q-rows (4 warps x 32 rows, MT=2), FBK=64.
// B-fragments (K, V) loaded once per warp and reused across both mt-blocks:
// K/V smem fragment traffic per q-row is halved vs MT=1.
// smem ~88 KB -> 2 CTAs/SM.
// ---------------------------------------------------------------------------
constexpr int FBQ = 128;
constexpr int FBK = 64;
constexpr int FQS = 68;     // Q row stride
constexpr int FKS = 68;     // K / P row stride
constexpr int FVS = 72;     // V row stride (8*tig+g conflict-free frag loads)
constexpr int FSMEM_WORDS = FBQ * FQS + FBQ * FKS + FBK * FVS + FBK;
constexpr int FSMEM_BYTES = FSMEM_WORDS * 4;   // (8704+8704+4608+64)*4 = 88320

__global__ void __launch_bounds__(128) flash_kernel(const int* __restrict__ mask)
{
    extern __shared__ float sm[];
    float* Qs   = sm;                     // [128][68]
    float* KP   = Qs + FBQ * FQS;         // K [64][68] / P [128][68]
    float* Vs   = KP + FBQ * FKS;         // [64][72]
    float* sAdd = Vs + FBK * FVS;         // [64]

    const int z = blockIdx.y;
    const int b = z >> 4, n = z & 15;
    const int q0 = blockIdx.x * FBQ;
    const int tid = threadIdx.x, lane = tid & 31, w = tid >> 5;
    const int g = lane >> 2, tig = lane & 3;
    const int wr = w * 32;                // warp's 32-row block

    const float* Qg = g_qh + (long long)b * S_ * D_ + n * H_;
    const float* Kg = g_kh + (long long)b * S_ * D_ + n * H_;
    const float* Vg = g_vh + (long long)b * S_ * D_ + n * H_;
    const float* cv = g_cvec + (long long)z * S_;
    const int*   mk = mask + b * S_;

    // Load Q tile (128 x 64) as tf32
#pragma unroll
    for (int i = 0; i < 16; i++) {
        int v = tid + i * 128;            // 128 rows * 16 float4
        int row = v >> 4, c4 = v & 15;
        float4 t = *reinterpret_cast<const float4*>(
            Qg + (long long)(q0 + row) * D_ + 4 * c4);
        float* p = Qs + row * FQS + 4 * c4;
        p[0] = __uint_as_float(f2tf(t.x)); p[1] = __uint_as_float(f2tf(t.y));
        p[2] = __uint_as_float(f2tf(t.z)); p[3] = __uint_as_float(f2tf(t.w));
    }

    float Oa[2][8][4];
#pragma unroll
    for (int mt = 0; mt < 2; mt++)
#pragma unroll
        for (int i = 0; i < 8; i++)
#pragma unroll
            for (int j = 0; j < 4; j++) Oa[mt][i][j] = 0.f;
    float mr[2][2], lr[2][2];
#pragma unroll
    for (int mt = 0; mt < 2; mt++) {
        mr[mt][0] = mr[mt][1] = -3.0e38f;
        lr[mt][0] = lr[mt][1] = 0.f;
    }

    for (int kt = 0; kt < S_ / FBK; kt++) {
        __syncthreads();   // prior-tile P/V reads done; Q store done (iter 0)
        const int kb = kt * FBK;
#pragma unroll
        for (int i = 0; i < 8; i++) {
            int v = tid + i * 128;        // 64 rows * 16 float4
            int row = v >> 4, c4 = v & 15;
            float4 t = *reinterpret_cast<const float4*>(
                Kg + (long long)(kb + row) * D_ + 4 * c4);
            float* p = KP + row * FKS + 4 * c4;
            p[0] = __uint_as_float(f2tf(t.x)); p[1] = __uint_as_float(f2tf(t.y));
            p[2] = __uint_as_float(f2tf(t.z)); p[3] = __uint_as_float(f2tf(t.w));
            float4 u = *reinterpret_cast<const float4*>(
                Vg + (long long)(kb + row) * D_ + 4 * c4);
            float* pv = Vs + row * FVS + 4 * c4;
            pv[0] = __uint_as_float(f2tf(u.x)); pv[1] = __uint_as_float(f2tf(u.y));
            pv[2] = __uint_as_float(f2tf(u.z)); pv[3] = __uint_as_float(f2tf(u.w));
        }
        if (tid < FBK)
            sAdd[tid] = NORM_ * cv[kb + tid] - BIGC_ * (float)mk[kb + tid];
        __syncthreads();

        // S = Q @ K^T : per-warp 32 x 64 (2 mt-blocks share each B-fragment)
        float Sa[2][8][4];
#pragma unroll
        for (int mt = 0; mt < 2; mt++)
#pragma unroll
            for (int i = 0; i < 8; i++)
#pragma unroll
                for (int j = 0; j < 4; j++) Sa[mt][i][j] = 0.f;
#pragma unroll
        for (int ks = 0; ks < 8; ks++) {
            uint32_t a[2][4];
#pragma unroll
            for (int mt = 0; mt < 2; mt++) {
                int rr = wr + mt * 16 + g;
                a[mt][0] = __float_as_uint(Qs[ rr      * FQS + ks * 8 + tig]);
                a[mt][1] = __float_as_uint(Qs[(rr + 8) * FQS + ks * 8 + tig]);
                a[mt][2] = __float_as_uint(Qs[ rr      * FQS + ks * 8 + tig + 4]);
                a[mt][3] = __float_as_uint(Qs[(rr + 8) * FQS + ks * 8 + tig + 4]);
            }
#pragma unroll
            for (int nt = 0; nt < 8; nt++) {
                uint32_t bfr[2];
                bfr[0] = __float_as_uint(KP[(nt * 8 + g) * FKS + ks * 8 + tig]);
                bfr[1] = __float_as_uint(KP[(nt * 8 + g) * FKS + ks * 8 + tig + 4]);
                mma8(Sa[0][nt], a[0], bfr);
                mma8(Sa[1][nt], a[1], bfr);
            }
        }
        __syncthreads();   // all warps finished reading K from KP

        // Epilogue + online softmax (per mt-block, rows rr+g / rr+g+8)
#pragma unroll
        for (int mt = 0; mt < 2; mt++) {
            const int rr = wr + mt * 16 + g;
            float tm0 = -3.0e38f, tm1 = -3.0e38f;
#pragma unroll
            for (int nt = 0; nt < 8; nt++) {
                int c = nt * 8 + 2 * tig;
                float a0 = sAdd[c], a1 = sAdd[c + 1];
                Sa[mt][nt][0] = NORM_ * Sa[mt][nt][0] + a0;
                Sa[mt][nt][1] = NORM_ * Sa[mt][nt][1] + a1;
                Sa[mt][nt][2] = NORM_ * Sa[mt][nt][2] + a0;
                Sa[mt][nt][3] = NORM_ * Sa[mt][nt][3] + a1;
                tm0 = fmaxf(tm0, fmaxf(Sa[mt][nt][0], Sa[mt][nt][1]));
                tm1 = fmaxf(tm1, fmaxf(Sa[mt][nt][2], Sa[mt][nt][3]));
            }
            tm0 = fmaxf(tm0, __shfl_xor_sync(~0u, tm0, 1));
            tm0 = fmaxf(tm0, __shfl_xor_sync(~0u, tm0, 2));
            tm1 = fmaxf(tm1, __shfl_xor_sync(~0u, tm1, 1));
            tm1 = fmaxf(tm1, __shfl_xor_sync(~0u, tm1, 2));
            float mn0 = fmaxf(mr[mt][0], tm0), mn1 = fmaxf(mr[mt][1], tm1);
            float sc0 = __expf(mr[mt][0] - mn0), sc1 = __expf(mr[mt][1] - mn1);
            mr[mt][0] = mn0; mr[mt][1] = mn1;

            float rs0 = 0.f, rs1 = 0.f;
#pragma unroll
            for (int nt = 0; nt < 8; nt++) {
                int c = nt * 8 + 2 * tig;
                float p0 = __expf(Sa[mt][nt][0] - mn0);
                float p1 = __expf(Sa[mt][nt][1] - mn0);
                float p2 = __expf(Sa[mt][nt][2] - mn1);
                float p3 = __expf(Sa[mt][nt][3] - mn1);
                rs0 += p0 + p1; rs1 += p2 + p3;
                KP[ rr      * FKS + c    ] = __uint_as_float(f2tf(p0));
                KP[ rr      * FKS + c + 1] = __uint_as_float(f2tf(p1));
                KP[(rr + 8) * FKS + c    ] = __uint_as_float(f2tf(p2));
                KP[(rr + 8) * FKS + c + 1] = __uint_as_float(f2tf(p3));
            }
            rs0 += __shfl_xor_sync(~0u, rs0, 1);
            rs0 += __shfl_xor_sync(~0u, rs0, 2);
            rs1 += __shfl_xor_sync(~0u, rs1, 1);
            rs1 += __shfl_xor_sync(~0u, rs1, 2);
            lr[mt][0] = lr[mt][0] * sc0 + rs0;
            lr[mt][1] = lr[mt][1] * sc1 + rs1;
#pragma unroll
            for (int nt = 0; nt < 8; nt++) {
                Oa[mt][nt][0] *= sc0; Oa[mt][nt][1] *= sc0;
                Oa[mt][nt][2] *= sc1; Oa[mt][nt][3] *= sc1;
            }
        }
        __syncwarp();      // P visible within warp (A-frags are own 32 rows)

        // O += P(32x64) @ V(64x64), V-fragments shared across mt-blocks
#pragma unroll
        for (int ks = 0; ks < 8; ks++) {
            uint32_t a[2][4];
#pragma unroll
            for (int mt = 0; mt < 2; mt++) {
                int rr = wr + mt * 16 + g;
                a[mt][0] = __float_as_uint(KP[ rr      * FKS + ks * 8 + tig]);
                a[mt][1] = __float_as_uint(KP[(rr + 8) * FKS + ks * 8 + tig]);
                a[mt][2] = __float_as_uint(KP[ rr      * FKS + ks * 8 + tig + 4]);
                a[mt][3] = __float_as_uint(KP[(rr + 8) * FKS + ks * 8 + tig + 4]);
            }
#pragma unroll
            for (int nt = 0; nt < 8; nt++) {
                uint32_t bfr[2];
                bfr[0] = __float_as_uint(Vs[(ks * 8 + tig    ) * FVS + nt * 8 + g]);
                bfr[1] = __float_as_uint(Vs[(ks * 8 + tig + 4) * FVS + nt * 8 + g]);
                mma8(Oa[0][nt], a[0], bfr);
                mma8(Oa[1][nt], a[1], bfr);
            }
        }
    }

    // Normalize and write out
    float* Og = g_out + (long long)b * S_ * D_ + n * H_;
#pragma unroll
    for (int mt = 0; mt < 2; mt++) {
        const int rr = wr + mt * 16 + g;
        const float inv0 = 1.0f / lr[mt][0], inv1 = 1.0f / lr[mt][1];
#pragma unroll
        for (int nt = 0; nt < 8; nt++) {
            int col = nt * 8 + 2 * tig;
            *reinterpret_cast<float2*>(
                Og + (long long)(q0 + rr) * D_ + col) =
                make_float2(Oa[mt][nt][0] * inv0, Oa[mt][nt][1] * inv0);
            *reinterpret_cast<float2*>(
                Og + (long long)(q0 + rr + 8) * D_ + col) =
                make_float2(Oa[mt][nt][2] * inv1, Oa[mt][nt][3] * inv1);
        }
    }
}

// ---------------------------------------------------------------------------
// LayerNorm in place on d_out rows. One block (256 thr) per row.
// ---------------------------------------------------------------------------
__global__ void __launch_bounds__(256)
ln_kernel(float* __restrict__ x, const float* __restrict__ gamma,
          const float* __restrict__ beta)
{
    float* p = x + (long long)blockIdx.x * D_;
    const int t = threadIdx.x;
    __shared__ float sred[8];

    float v[4];
    float s = 0.f;
#pragma unroll
    for (int i = 0; i < 4; i++) { v[i] = p[t + 256 * i]; s += v[i]; }
#pragma unroll
    for (int o = 16; o; o >>= 1) s += __shfl_xor_sync(~0u, s, o);
    if ((t & 31) == 0) sred[t >> 5] = s;
    __syncthreads();
    s = 0.f;
#pragma unroll
    for (int i = 0; i < 8; i++) s += sred[i];
    const float mean = s * (1.0f / D_);
    __syncthreads();

    float vs = 0.f;
#pragma unroll
    for (int i = 0; i < 4; i++) { float d = v[i] - mean; vs += d * d; }
#pragma unroll
    for (int o = 16; o; o >>= 1) vs += __shfl_xor_sync(~0u, vs, o);
    if ((t & 31) == 0) sred[t >> 5] = vs;
    __syncthreads();
    vs = 0.f;
#pragma unroll
    for (int i = 0; i < 8; i++) vs += sred[i];
    const float rstd = rsqrtf(vs * (1.0f / D_) + LNEPS_);

#pragma unroll
    for (int i = 0; i < 4; i++) {
        const int col = t + 256 * i;
        p[col] = (v[i] - mean) * rstd * gamma[col] + beta[col];
    }
}

// ---------------------------------------------------------------------------
// Host launcher
// ---------------------------------------------------------------------------
extern "C" void kernel_launch(void* const* d_in, const int* in_sizes, int n_in,
                              void* d_out, int out_size)
{
    const float* q        = (const float*)d_in[0];
    const float* k        = (const float*)d_in[1];
    const float* v        = (const float*)d_in[2];
    const float* pos_enc  = (const float*)d_in[3];
    const int*   mask     = (const int*)  d_in[4];
    const float* q_w      = (const float*)d_in[5];
    const float* k_w      = (const float*)d_in[6];
    const float* k_b      = (const float*)d_in[7];
    const float* v_w      = (const float*)d_in[8];
    const float* v_b      = (const float*)d_in[9];
    const float* rwb      = (const float*)d_in[10];
    const float* rrb      = (const float*)d_in[11];
    const float* r_kernel = (const float*)d_in[12];
    const float* post_w   = (const float*)d_in[13];
    const float* post_b   = (const float*)d_in[14];
    const float* ln_g     = (const float*)d_in[15];
    const float* ln_b     = (const float*)d_in[16];
    float* out = (float*)d_out;

    void* p;
    cudaGetSymbolAddress(&p, g_qh);     float* qh = (float*)p;
    cudaGetSymbolAddress(&p, g_kh);     float* kh = (float*)p;
    cudaGetSymbolAddress(&p, g_vh);     float* vh = (float*)p;
    cudaGetSymbolAddress(&p, g_r);      float* rr = (float*)p;
    cudaGetSymbolAddress(&p, g_rw);     float* rw = (float*)p;
    cudaGetSymbolAddress(&p, g_out);    float* ao = (float*)p;

    // 0. r_kernel transpose [N,D,H] -> [D, N*H]
    rk_transpose<<<64, 256>>>(r_kernel);

    // 1. Merged projections: z = {q, k, v, r(pos_enc)} in one launch
    {
        GemmBatch4 bs;
        bs.b[0] = { q,       q_w, nullptr, qh, B_ * S_ };
        bs.b[1] = { k,       k_w, k_b,     kh, B_ * S_ };
        bs.b[2] = { v,       v_w, v_b,     vh, B_ * S_ };
        bs.b[3] = { pos_enc, rw,  nullptr, rr, S_      };
        dim3 grid(D_ / 64, (B_ * S_) / 128, 4);
        tgemm_multi<128, 64, 4, 2><<<grid, 256>>>(bs, D_, D_, D_, D_);
    }

    // 2. KS = kh + r; cvec
    ks_cvec_kernel<<<(B_ * N_ * S_) / 8, 256>>>(rwb, rrb);

    // 3. Fused flash attention (scores + softmax + P@V) -> g_out
    {
        cudaFuncSetAttribute(flash_kernel,
                             cudaFuncAttributeMaxDynamicSharedMemorySize,
                             FSMEM_BYTES);
        dim3 grid(S_ / FBQ, B_ * N_);
        flash_kernel<<<grid, 128, FSMEM_BYTES>>>(mask);
    }

    // 4. post GEMM + bias + residual -> d_out
    {
        dim3 grid(D_ / 64, (B_ * S_) / 128, 1);
        tgemm<128, 64, 4, 2><<<grid, 256>>>(
            ao, post_w, out, D_, D_, D_, D_, post_b, q, D_);
    }

    // 5. LayerNorm in place
    ln_kernel<<<B_ * S_, 256>>>(out, ln_g, ln_b);
}

// round 12
// speedup vs baseline: 11.4534x; 1.3370x over previous
#include <cuda_runtime.h>
#include <cuda_bf16.h>
#include <math.h>
#include <stdint.h>

// Problem constants
constexpr int B_ = 2, S_ = 1024, D_ = 1024, N_ = 16, H_ = 64;
constexpr int DW = D_ / 2;            // packed bf16x2 words per row
constexpr float NORM_ = 0.125f;
constexpr float BIGC_ = 1000000.0f;
constexpr float LNEPS_ = 1e-5f;

// Scratch (static device globals — no runtime allocation)
__device__ __align__(16) uint32_t g_qhw[B_ * S_ * DW];   // qh packed bf16x2 (pairs along h)
__device__ __align__(16) uint32_t g_khw[B_ * S_ * DW];   // kh -> KS packed
__device__ __align__(16) float    g_vh [B_ * S_ * D_];   // vh fp32 (flash packs along s)
__device__ __align__(16) uint32_t g_rp [S_ * DW];        // r packed
__device__ __align__(16) float    g_rw [D_ * D_];        // r_kernel transposed [D, N*H]
__device__ __align__(16) float    g_cvec[B_ * N_ * S_];
__device__ __align__(16) uint32_t g_ow [B_ * S_ * DW];   // attn out packed

// ---------------------------------------------------------------------------
// bf16 helpers
// ---------------------------------------------------------------------------
__device__ __forceinline__ uint32_t pk(float a, float b) {
    __nv_bfloat162 t = __floats2bfloat162_rn(a, b);
    return *reinterpret_cast<uint32_t*>(&t);
}
__device__ __forceinline__ float2 upk(uint32_t w) {
    __nv_bfloat162 t = *reinterpret_cast<__nv_bfloat162*>(&w);
    return __bfloat1622float2(t);
}
// m16n8k16 bf16 mma, fp32 accumulate
__device__ __forceinline__ void mma16(float* c, const uint32_t* a, const uint32_t* b) {
    asm volatile(
        "mma.sync.aligned.m16n8k16.row.col.f32.bf16.bf16.f32 "
        "{%0,%1,%2,%3},{%4,%5,%6,%7},{%8,%9},{%0,%1,%2,%3};\n"
        : "+f"(c[0]), "+f"(c[1]), "+f"(c[2]), "+f"(c[3])
        : "r"(a[0]), "r"(a[1]), "r"(a[2]), "r"(a[3]), "r"(b[0]), "r"(b[1]));
}

// ---------------------------------------------------------------------------
// r_kernel transpose: [N, D, H] -> g_rw [D, N*H] (fp32).
// ---------------------------------------------------------------------------
__global__ void rk_transpose(const float* __restrict__ rk)
{
    const int idx = blockIdx.x * blockDim.x + threadIdx.x;   // 0 .. 16383
    const int d = idx >> 4, n = idx & 15;
    const float4* src = reinterpret_cast<const float4*>(
        rk + ((long long)n * D_ + d) * H_);
    float4* dst = reinterpret_cast<float4*>(g_rw + (long long)d * D_ + n * H_);
#pragma unroll
    for (int i = 0; i < 16; i++) dst[i] = src[i];
}

// ---------------------------------------------------------------------------
// Multi-batch NN bf16 GEMM (one launch for q/k/v/r projections).
// A fp32 [M,K], B fp32 [K,N-slice]; smem holds bf16x2 words (8 words / k16).
// pack!=0: C is packed bf16x2 words; else fp32.
// ---------------------------------------------------------------------------
struct GemmBatch {
    const float* A;
    const float* Bm;
    const float* bias;
    void*        C;
    int          M;
    int          pack;
};
struct GemmBatch4 { GemmBatch b[4]; };

template <int BM, int BN, int WMS, int WNS>
__global__ void __launch_bounds__(WMS * WNS * 32)
tgemm_multi(GemmBatch4 bs, int K, int lda, int ldb)
{
    constexpr int NTHR = WMS * WNS * 32;
    constexpr int BKW  = 12;            // 8 words (k16) + pad 4
    constexpr int WTM  = BM / WMS, WTN = BN / WNS;
    constexpr int MT   = WTM / 16, NT2 = WTN / 8;
    constexpr int AV   = 4 * BM / NTHR;
    constexpr int BV   = 4 * BN / NTHR;

    const GemmBatch P = bs.b[blockIdx.z];
    const int m0 = blockIdx.y * BM, n0 = blockIdx.x * BN;
    if (m0 >= P.M) return;

    __shared__ uint32_t As[2][BM][BKW];
    __shared__ uint32_t Bs[2][BN][BKW];

    const float* A  = P.A;
    const float* Bm = P.Bm;

    const int tid = threadIdx.x, lane = tid & 31, wid = tid >> 5;
    const int g = lane >> 2, tig = lane & 3;
    const int wm = wid / WNS, wn = wid % WNS;

    float4 aSt[AV];
    float  bSt[BV][4];
    const int NK = K / 16;

    auto loadG = [&](int k0) {
#pragma unroll
        for (int i = 0; i < AV; i++) {
            int v = tid + i * NTHR; int row = v >> 2, c4 = v & 3;
            aSt[i] = *reinterpret_cast<const float4*>(
                A + (long long)(m0 + row) * lda + k0 + 4 * c4);
        }
#pragma unroll
        for (int i = 0; i < BV; i++) {
            int n = tid % BN; int kb = tid / BN + i * (NTHR / BN);
#pragma unroll
            for (int j = 0; j < 4; j++)
                bSt[i][j] = Bm[(long long)(k0 + kb * 4 + j) * ldb + n0 + n];
        }
    };

    auto storeS = [&](int st) {
#pragma unroll
        for (int i = 0; i < AV; i++) {
            int v = tid + i * NTHR; int row = v >> 2, c4 = v & 3;
            As[st][row][2 * c4    ] = pk(aSt[i].x, aSt[i].y);
            As[st][row][2 * c4 + 1] = pk(aSt[i].z, aSt[i].w);
        }
#pragma unroll
        for (int i = 0; i < BV; i++) {
            int n = tid % BN; int kb = tid / BN + i * (NTHR / BN);
            Bs[st][n][2 * kb    ] = pk(bSt[i][0], bSt[i][1]);
            Bs[st][n][2 * kb + 1] = pk(bSt[i][2], bSt[i][3]);
        }
    };

    float acc[MT][NT2][4];
#pragma unroll
    for (int mt = 0; mt < MT; mt++)
#pragma unroll
        for (int nt = 0; nt < NT2; nt++)
#pragma unroll
            for (int j = 0; j < 4; j++) acc[mt][nt][j] = 0.f;

    auto comp = [&](int st) {
        uint32_t af[MT][4], bf[NT2][2];
#pragma unroll
        for (int mt = 0; mt < MT; mt++) {
            int r0 = wm * WTM + mt * 16 + g;
            af[mt][0] = As[st][r0    ][tig];
            af[mt][1] = As[st][r0 + 8][tig];
            af[mt][2] = As[st][r0    ][tig + 4];
            af[mt][3] = As[st][r0 + 8][tig + 4];
        }
#pragma unroll
        for (int nt = 0; nt < NT2; nt++) {
            int c0 = wn * WTN + nt * 8 + g;
            bf[nt][0] = Bs[st][c0][tig];
            bf[nt][1] = Bs[st][c0][tig + 4];
        }
#pragma unroll
        for (int mt = 0; mt < MT; mt++)
#pragma unroll
            for (int nt = 0; nt < NT2; nt++)
                mma16(acc[mt][nt], af[mt], bf[nt]);
    };

    loadG(0); storeS(0); __syncthreads();
    int cur = 0;
    for (int it = 1; it <= NK; it++) {
        if (it < NK) loadG(it * 16);
        comp(cur);
        if (it < NK) storeS(cur ^ 1);
        __syncthreads();
        cur ^= 1;
    }

#pragma unroll
    for (int mt = 0; mt < MT; mt++) {
        int r0 = m0 + wm * WTM + mt * 16 + g;
#pragma unroll
        for (int nt = 0; nt < NT2; nt++) {
            int col = n0 + wn * WTN + nt * 8 + 2 * tig;
            float v0 = acc[mt][nt][0], v1 = acc[mt][nt][1];
            float v2 = acc[mt][nt][2], v3 = acc[mt][nt][3];
            if (P.bias) {
                float b0f = P.bias[col], b1f = P.bias[col + 1];
                v0 += b0f; v1 += b1f; v2 += b0f; v3 += b1f;
            }
            if (P.pack) {
                uint32_t* Cw = (uint32_t*)P.C;
                Cw[(long long)r0 * DW + (col >> 1)]       = pk(v0, v1);
                Cw[(long long)(r0 + 8) * DW + (col >> 1)] = pk(v2, v3);
            } else {
                float* Cf = (float*)P.C;
                *reinterpret_cast<float2*>(&Cf[(long long)r0 * D_ + col]) =
                    make_float2(v0, v1);
                *reinterpret_cast<float2*>(&Cf[(long long)(r0 + 8) * D_ + col]) =
                    make_float2(v2, v3);
            }
        }
    }
}

// ---------------------------------------------------------------------------
// Post GEMM: A packed bf16x2 [M, DW], B fp32 [K,N]; out fp32 + bias + resid.
// ---------------------------------------------------------------------------
template <int BM, int BN, int WMS, int WNS>
__global__ void __launch_bounds__(WMS * WNS * 32)
tgemm_post(const uint32_t* __restrict__ Aw, const float* __restrict__ Bm,
           float* __restrict__ C, int K, int ldb,
           const float* __restrict__ colBias,
           const float* __restrict__ resid)
{
    constexpr int NTHR = WMS * WNS * 32;
    constexpr int BKW  = 12;
    constexpr int WTM  = BM / WMS, WTN = BN / WNS;
    constexpr int MT   = WTM / 16, NT2 = WTN / 8;
    constexpr int AV   = 4 * BM / NTHR;
    constexpr int BV   = 4 * BN / NTHR;

    __shared__ uint32_t As[2][BM][BKW];
    __shared__ uint32_t Bs[2][BN][BKW];

    const int m0 = blockIdx.y * BM, n0 = blockIdx.x * BN;
    const int tid = threadIdx.x, lane = tid & 31, wid = tid >> 5;
    const int g = lane >> 2, tig = lane & 3;
    const int wm = wid / WNS, wn = wid % WNS;

    uint2 aSt[AV];
    float bSt[BV][4];
    const int NK = K / 16;

    auto loadG = [&](int k0) {
#pragma unroll
        for (int i = 0; i < AV; i++) {
            int v = tid + i * NTHR; int row = v >> 2, c4 = v & 3;
            aSt[i] = *reinterpret_cast<const uint2*>(
                Aw + (long long)(m0 + row) * DW + (k0 >> 1) + 2 * c4);
        }
#pragma unroll
        for (int i = 0; i < BV; i++) {
            int n = tid % BN; int kb = tid / BN + i * (NTHR / BN);
#pragma unroll
            for (int j = 0; j < 4; j++)
                bSt[i][j] = Bm[(long long)(k0 + kb * 4 + j) * ldb + n0 + n];
        }
    };

    auto storeS = [&](int st) {
#pragma unroll
        for (int i = 0; i < AV; i++) {
            int v = tid + i * NTHR; int row = v >> 2, c4 = v & 3;
            As[st][row][2 * c4    ] = aSt[i].x;
            As[st][row][2 * c4 + 1] = aSt[i].y;
        }
#pragma unroll
        for (int i = 0; i < BV; i++) {
            int n = tid % BN; int kb = tid / BN + i * (NTHR / BN);
            Bs[st][n][2 * kb    ] = pk(bSt[i][0], bSt[i][1]);
            Bs[st][n][2 * kb + 1] = pk(bSt[i][2], bSt[i][3]);
        }
    };

    float acc[MT][NT2][4];
#pragma unroll
    for (int mt = 0; mt < MT; mt++)
#pragma unroll
        for (int nt = 0; nt < NT2; nt++)
#pragma unroll
            for (int j = 0; j < 4; j++) acc[mt][nt][j] = 0.f;

    auto comp = [&](int st) {
        uint32_t af[MT][4], bf[NT2][2];
#pragma unroll
        for (int mt = 0; mt < MT; mt++) {
            int r0 = wm * WTM + mt * 16 + g;
            af[mt][0] = As[st][r0    ][tig];
            af[mt][1] = As[st][r0 + 8][tig];
            af[mt][2] = As[st][r0    ][tig + 4];
            af[mt][3] = As[st][r0 + 8][tig + 4];
        }
#pragma unroll
        for (int nt = 0; nt < NT2; nt++) {
            int c0 = wn * WTN + nt * 8 + g;
            bf[nt][0] = Bs[st][c0][tig];
            bf[nt][1] = Bs[st][c0][tig + 4];
        }
#pragma unroll
        for (int mt = 0; mt < MT; mt++)
#pragma unroll
            for (int nt = 0; nt < NT2; nt++)
                mma16(acc[mt][nt], af[mt], bf[nt]);
    };

    loadG(0); storeS(0); __syncthreads();
    int cur = 0;
    for (int it = 1; it <= NK; it++) {
        if (it < NK) loadG(it * 16);
        comp(cur);
        if (it < NK) storeS(cur ^ 1);
        __syncthreads();
        cur ^= 1;
    }

#pragma unroll
    for (int mt = 0; mt < MT; mt++) {
        int r0 = m0 + wm * WTM + mt * 16 + g;
#pragma unroll
        for (int nt = 0; nt < NT2; nt++) {
            int col = n0 + wn * WTN + nt * 8 + 2 * tig;
            float v0 = acc[mt][nt][0], v1 = acc[mt][nt][1];
            float v2 = acc[mt][nt][2], v3 = acc[mt][nt][3];
            float b0f = colBias[col], b1f = colBias[col + 1];
            v0 += b0f + resid[(long long)r0 * D_ + col];
            v1 += b1f + resid[(long long)r0 * D_ + col + 1];
            v2 += b0f + resid[(long long)(r0 + 8) * D_ + col];
            v3 += b1f + resid[(long long)(r0 + 8) * D_ + col + 1];
            *reinterpret_cast<float2*>(&C[(long long)r0 * D_ + col]) =
                make_float2(v0, v1);
            *reinterpret_cast<float2*>(&C[(long long)(r0 + 8) * D_ + col]) =
                make_float2(v2, v3);
        }
    }
}

// ---------------------------------------------------------------------------
// Fused KS / cvec on packed arrays. One warp per (b,n,s); lane l owns word l
// of the 32-word (H=64) head slice.
// ---------------------------------------------------------------------------
__global__ void ks_cvec_kernel(const float* __restrict__ rwb,
                               const float* __restrict__ rrb)
{
    const int gw = (blockIdx.x * blockDim.x + threadIdx.x) >> 5;
    const int lane = threadIdx.x & 31;
    if (gw >= B_ * N_ * S_) return;
    const int s = gw % S_;
    const int n = (gw / S_) % N_;
    const int b = gw / (S_ * N_);

    const long long khI = (long long)(b * S_ + s) * DW + n * 32 + lane;
    const long long rI  = (long long)s * DW + n * 32 + lane;

    float2 kv = upk(g_khw[khI]);
    float2 rv = upk(g_rp[rI]);
    g_khw[khI] = pk(kv.x + rv.x, kv.y + rv.y);

    const int hb = n * H_ + 2 * lane;
    float acc = rwb[hb] * kv.x + rwb[hb + 1] * kv.y
              + rrb[hb] * rv.x + rrb[hb + 1] * rv.y;
#pragma unroll
    for (int o = 16; o; o >>= 1) acc += __shfl_xor_sync(~0u, acc, o);
    if (lane == 0) g_cvec[(long long)(b * N_ + n) * S_ + s] = acc;
}

// ---------------------------------------------------------------------------
// Fused flash attention, bf16 operands. FBQ=128 (4 warps x 32 rows, MT=2),
// FBK=64. Word strides: Q/K/P rows 36 (32+4), V word-rows 72.
// smem ~46.3 KB.
// ---------------------------------------------------------------------------
constexpr int FBQ = 128;
constexpr int FBK = 64;
constexpr int QWS = 36;     // Q/K/P word stride
constexpr int VWS = 72;     // V word stride
constexpr int FSMEM_WORDS = FBQ * QWS + FBQ * QWS + (FBK / 2) * VWS + FBK;
constexpr int FSMEM_BYTES = FSMEM_WORDS * 4;   // (4608+4608+2304+64)*4 = 46336

__global__ void __launch_bounds__(128) flash_kernel(const int* __restrict__ mask)
{
    extern __shared__ uint32_t smw[];
    uint32_t* Qs   = smw;                       // [128][36]
    uint32_t* KP   = Qs + FBQ * QWS;            // K [64][36] / P [128][36]
    uint32_t* Vs   = KP + FBQ * QWS;            // [32][72] (s-pairs x h)
    float*    sAdd = reinterpret_cast<float*>(Vs + (FBK / 2) * VWS);  // [64]

    const int z = blockIdx.y;
    const int b = z >> 4, n = z & 15;
    const int q0 = blockIdx.x * FBQ;
    const int tid = threadIdx.x, lane = tid & 31, w = tid >> 5;
    const int g = lane >> 2, tig = lane & 3;
    const int wr = w * 32;

    const uint32_t* Qg = g_qhw + (long long)b * S_ * DW + n * 32;
    const uint32_t* Kg = g_khw + (long long)b * S_ * DW + n * 32;
    const float*    Vg = g_vh  + (long long)b * S_ * D_ + n * H_;
    const float*    cv = g_cvec + (long long)z * S_;
    const int*      mk = mask + b * S_;

    // Load Q tile (128 rows x 32 words)
#pragma unroll
    for (int i = 0; i < 8; i++) {
        int v = tid + i * 128;            // 128 rows * 8 uint4
        int row = v >> 3, c = v & 7;
        uint4 t = *reinterpret_cast<const uint4*>(
            Qg + (long long)(q0 + row) * DW + 4 * c);
        *reinterpret_cast<uint4*>(Qs + row * QWS + 4 * c) = t;
    }

    float Oa[2][8][4];
#pragma unroll
    for (int mt = 0; mt < 2; mt++)
#pragma unroll
        for (int i = 0; i < 8; i++)
#pragma unroll
            for (int j = 0; j < 4; j++) Oa[mt][i][j] = 0.f;
    float mr[2][2], lr[2][2];
#pragma unroll
    for (int mt = 0; mt < 2; mt++) {
        mr[mt][0] = mr[mt][1] = -3.0e38f;
        lr[mt][0] = lr[mt][1] = 0.f;
    }

    for (int kt = 0; kt < S_ / FBK; kt++) {
        __syncthreads();   // prior-tile P/V reads done; Q store done (iter 0)
        const int kb = kt * FBK;
        // K tile: 64 rows x 8 uint4 = 512 tasks
#pragma unroll
        for (int i = 0; i < 4; i++) {
            int v = tid + i * 128;
            int row = v >> 3, c = v & 7;
            uint4 t = *reinterpret_cast<const uint4*>(
                Kg + (long long)(kb + row) * DW + 4 * c);
            *reinterpret_cast<uint4*>(KP + row * QWS + 4 * c) = t;
        }
        // V tile: pack pairs along s. 32 word-rows x 16 float4-cols = 512 tasks
#pragma unroll
        for (int i = 0; i < 4; i++) {
            int v = tid + i * 128;
            int sw = v >> 4, h4 = v & 15;
            float4 r0v = *reinterpret_cast<const float4*>(
                Vg + (long long)(kb + 2 * sw) * D_ + 4 * h4);
            float4 r1v = *reinterpret_cast<const float4*>(
                Vg + (long long)(kb + 2 * sw + 1) * D_ + 4 * h4);
            uint4 o;
            o.x = pk(r0v.x, r1v.x); o.y = pk(r0v.y, r1v.y);
            o.z = pk(r0v.z, r1v.z); o.w = pk(r0v.w, r1v.w);
            *reinterpret_cast<uint4*>(Vs + sw * VWS + 4 * h4) = o;
        }
        if (tid < FBK)
            sAdd[tid] = NORM_ * cv[kb + tid] - BIGC_ * (float)mk[kb + tid];
        __syncthreads();

        // S = Q @ K^T : per-warp 32 x 64, 4 k16 blocks
        float Sa[2][8][4];
#pragma unroll
        for (int mt = 0; mt < 2; mt++)
#pragma unroll
            for (int i = 0; i < 8; i++)
#pragma unroll
                for (int j = 0; j < 4; j++) Sa[mt][i][j] = 0.f;
#pragma unroll
        for (int ks = 0; ks < 4; ks++) {
            uint32_t a[2][4];
#pragma unroll
            for (int mt = 0; mt < 2; mt++) {
                int rr = wr + mt * 16 + g;
                a[mt][0] = Qs[ rr      * QWS + ks * 8 + tig];
                a[mt][1] = Qs[(rr + 8) * QWS + ks * 8 + tig];
                a[mt][2] = Qs[ rr      * QWS + ks * 8 + tig + 4];
                a[mt][3] = Qs[(rr + 8) * QWS + ks * 8 + tig + 4];
            }
#pragma unroll
            for (int nt = 0; nt < 8; nt++) {
                uint32_t bfr[2];
                bfr[0] = KP[(nt * 8 + g) * QWS + ks * 8 + tig];
                bfr[1] = KP[(nt * 8 + g) * QWS + ks * 8 + tig + 4];
                mma16(Sa[0][nt], a[0], bfr);
                mma16(Sa[1][nt], a[1], bfr);
            }
        }
        __syncthreads();   // all warps finished reading K from KP

        // Epilogue + online softmax; P packed into KP
#pragma unroll
        for (int mt = 0; mt < 2; mt++) {
            const int rr = wr + mt * 16 + g;
            float tm0 = -3.0e38f, tm1 = -3.0e38f;
#pragma unroll
            for (int nt = 0; nt < 8; nt++) {
                int c = nt * 8 + 2 * tig;
                float a0 = sAdd[c], a1 = sAdd[c + 1];
                Sa[mt][nt][0] = NORM_ * Sa[mt][nt][0] + a0;
                Sa[mt][nt][1] = NORM_ * Sa[mt][nt][1] + a1;
                Sa[mt][nt][2] = NORM_ * Sa[mt][nt][2] + a0;
                Sa[mt][nt][3] = NORM_ * Sa[mt][nt][3] + a1;
                tm0 = fmaxf(tm0, fmaxf(Sa[mt][nt][0], Sa[mt][nt][1]));
                tm1 = fmaxf(tm1, fmaxf(Sa[mt][nt][2], Sa[mt][nt][3]));
            }
            tm0 = fmaxf(tm0, __shfl_xor_sync(~0u, tm0, 1));
            tm0 = fmaxf(tm0, __shfl_xor_sync(~0u, tm0, 2));
            tm1 = fmaxf(tm1, __shfl_xor_sync(~0u, tm1, 1));
            tm1 = fmaxf(tm1, __shfl_xor_sync(~0u, tm1, 2));
            float mn0 = fmaxf(mr[mt][0], tm0), mn1 = fmaxf(mr[mt][1], tm1);
            float sc0 = __expf(mr[mt][0] - mn0), sc1 = __expf(mr[mt][1] - mn1);
            mr[mt][0] = mn0; mr[mt][1] = mn1;

            float rs0 = 0.f, rs1 = 0.f;
#pragma unroll
            for (int nt = 0; nt < 8; nt++) {
                float p0 = __expf(Sa[mt][nt][0] - mn0);
                float p1 = __expf(Sa[mt][nt][1] - mn0);
                float p2 = __expf(Sa[mt][nt][2] - mn1);
                float p3 = __expf(Sa[mt][nt][3] - mn1);
                rs0 += p0 + p1; rs1 += p2 + p3;
                KP[ rr      * QWS + nt * 4 + tig] = pk(p0, p1);
                KP[(rr + 8) * QWS + nt * 4 + tig] = pk(p2, p3);
            }
            rs0 += __shfl_xor_sync(~0u, rs0, 1);
            rs0 += __shfl_xor_sync(~0u, rs0, 2);
            rs1 += __shfl_xor_sync(~0u, rs1, 1);
            rs1 += __shfl_xor_sync(~0u, rs1, 2);
            lr[mt][0] = lr[mt][0] * sc0 + rs0;
            lr[mt][1] = lr[mt][1] * sc1 + rs1;
#pragma unroll
            for (int nt = 0; nt < 8; nt++) {
                Oa[mt][nt][0] *= sc0; Oa[mt][nt][1] *= sc0;
                Oa[mt][nt][2] *= sc1; Oa[mt][nt][3] *= sc1;
            }
        }
        __syncwarp();      // P visible within warp (A-frags are own 32 rows)

        // O += P(32x64) @ V(64x64): 4 k16 blocks
#pragma unroll
        for (int ks = 0; ks < 4; ks++) {
            uint32_t a[2][4];
#pragma unroll
            for (int mt = 0; mt < 2; mt++) {
                int rr = wr + mt * 16 + g;
                a[mt][0] = KP[ rr      * QWS + ks * 8 + tig];
                a[mt][1] = KP[(rr + 8) * QWS + ks * 8 + tig];
                a[mt][2] = KP[ rr      * QWS + ks * 8 + tig + 4];
                a[mt][3] = KP[(rr + 8) * QWS + ks * 8 + tig + 4];
            }
#pragma unroll
            for (int nt = 0; nt < 8; nt++) {
                uint32_t bfr[2];
                bfr[0] = Vs[(ks * 8 + tig    ) * VWS + nt * 8 + g];
                bfr[1] = Vs[(ks * 8 + tig + 4) * VWS + nt * 8 + g];
                mma16(Oa[0][nt], a[0], bfr);
                mma16(Oa[1][nt], a[1], bfr);
            }
        }
    }

    // Normalize and write packed output
    uint32_t* Og = g_ow + (long long)b * S_ * DW + n * 32;
#pragma unroll
    for (int mt = 0; mt < 2; mt++) {
        const int rr = wr + mt * 16 + g;
        const float inv0 = 1.0f / lr[mt][0], inv1 = 1.0f / lr[mt][1];
#pragma unroll
        for (int nt = 0; nt < 8; nt++) {
            Og[(long long)(q0 + rr) * DW + nt * 4 + tig] =
                pk(Oa[mt][nt][0] * inv0, Oa[mt][nt][1] * inv0);
            Og[(long long)(q0 + rr + 8) * DW + nt * 4 + tig] =
                pk(Oa[mt][nt][2] * inv1, Oa[mt][nt][3] * inv1);
        }
    }
}

// ---------------------------------------------------------------------------
// LayerNorm in place on d_out rows. One block (256 thr) per row.
// ---------------------------------------------------------------------------
__global__ void __launch_bounds__(256)
ln_kernel(float* __restrict__ x, const float* __restrict__ gamma,
          const float* __restrict__ beta)
{
    float* p = x + (long long)blockIdx.x * D_;
    const int t = threadIdx.x;
    __shared__ float sred[8];

    float v[4];
    float s = 0.f;
#pragma unroll
    for (int i = 0; i < 4; i++) { v[i] = p[t + 256 * i]; s += v[i]; }
#pragma unroll
    for (int o = 16; o; o >>= 1) s += __shfl_xor_sync(~0u, s, o);
    if ((t & 31) == 0) sred[t >> 5] = s;
    __syncthreads();
    s = 0.f;
#pragma unroll
    for (int i = 0; i < 8; i++) s += sred[i];
    const float mean = s * (1.0f / D_);
    __syncthreads();

    float vs = 0.f;
#pragma unroll
    for (int i = 0; i < 4; i++) { float d = v[i] - mean; vs += d * d; }
#pragma unroll
    for (int o = 16; o; o >>= 1) vs += __shfl_xor_sync(~0u, vs, o);
    if ((t & 31) == 0) sred[t >> 5] = vs;
    __syncthreads();
    vs = 0.f;
#pragma unroll
    for (int i = 0; i < 8; i++) vs += sred[i];
    const float rstd = rsqrtf(vs * (1.0f / D_) + LNEPS_);

#pragma unroll
    for (int i = 0; i < 4; i++) {
        const int col = t + 256 * i;
        p[col] = (v[i] - mean) * rstd * gamma[col] + beta[col];
    }
}

// ---------------------------------------------------------------------------
// Host launcher
// ---------------------------------------------------------------------------
extern "C" void kernel_launch(void* const* d_in, const int* in_sizes, int n_in,
                              void* d_out, int out_size)
{
    const float* q        = (const float*)d_in[0];
    const float* k        = (const float*)d_in[1];
    const float* v        = (const float*)d_in[2];
    const float* pos_enc  = (const float*)d_in[3];
    const int*   mask     = (const int*)  d_in[4];
    const float* q_w      = (const float*)d_in[5];
    const float* k_w      = (const float*)d_in[6];
    const float* k_b      = (const float*)d_in[7];
    const float* v_w      = (const float*)d_in[8];
    const float* v_b      = (const float*)d_in[9];
    const float* rwb      = (const float*)d_in[10];
    const float* rrb      = (const float*)d_in[11];
    const float* r_kernel = (const float*)d_in[12];
    const float* post_w   = (const float*)d_in[13];
    const float* post_b   = (const float*)d_in[14];
    const float* ln_g     = (const float*)d_in[15];
    const float* ln_b     = (const float*)d_in[16];
    float* out = (float*)d_out;

    void* p;
    cudaGetSymbolAddress(&p, g_qhw); uint32_t* qhw = (uint32_t*)p;
    cudaGetSymbolAddress(&p, g_khw); uint32_t* khw = (uint32_t*)p;
    cudaGetSymbolAddress(&p, g_vh);  float*    vh  = (float*)p;
    cudaGetSymbolAddress(&p, g_rp);  uint32_t* rp  = (uint32_t*)p;
    cudaGetSymbolAddress(&p, g_rw);  float*    rw  = (float*)p;
    cudaGetSymbolAddress(&p, g_ow);  uint32_t* ow  = (uint32_t*)p;

    // 0. r_kernel transpose [N,D,H] -> [D, N*H]
    rk_transpose<<<64, 256>>>(r_kernel);

    // 1. Merged projections: z = {q, k, v, r(pos_enc)} in one launch
    {
        GemmBatch4 bs;
        bs.b[0] = { q,       q_w, nullptr, qhw, B_ * S_, 1 };
        bs.b[1] = { k,       k_w, k_b,     khw, B_ * S_, 1 };
        bs.b[2] = { v,       v_w, v_b,     vh,  B_ * S_, 0 };
        bs.b[3] = { pos_enc, rw,  nullptr, rp,  S_,      1 };
        dim3 grid(D_ / 64, (B_ * S_) / 128, 4);
        tgemm_multi<128, 64, 4, 2><<<grid, 256>>>(bs, D_, D_, D_);
    }

    // 2. KS = kh + r (packed); cvec
    ks_cvec_kernel<<<(B_ * N_ * S_) / 8, 256>>>(rwb, rrb);

    // 3. Fused flash attention (scores + softmax + P@V) -> g_ow
    {
        cudaFuncSetAttribute(flash_kernel,
                             cudaFuncAttributeMaxDynamicSharedMemorySize,
                             FSMEM_BYTES);
        dim3 grid(S_ / FBQ, B_ * N_);
        flash_kernel<<<grid, 128, FSMEM_BYTES>>>(mask);
    }

    // 4. post GEMM + bias + residual -> d_out
    {
        dim3 grid(D_ / 64, (B_ * S_) / 128, 1);
        tgemm_post<128, 64, 4, 2><<<grid, 256>>>(
            ow, post_w, out, D_, D_, post_b, q);
    }

    // 5. LayerNorm in place
    ln_kernel<<<B_ * S_, 256>>>(out, ln_g, ln_b);
}